// round 1
// baseline (speedup 1.0000x reference)
#include <cuda_runtime.h>

#define NB 2
#define NS 2048
#define ND 1024
#define NH 16
#define DP 64
#define MROWS (NB*NS)   // 4096

// ---------------- device scratch (allocation-free rule: __device__ globals) ---
__device__ __align__(16) float  g_qh[NB*NH*NS*DP];   // 16 MB  [B,H,S,d]
__device__ __align__(16) float  g_kh[NB*NH*NS*DP];   // 16 MB
__device__ __align__(16) float  g_vh[NB*NH*NS*DP];   // 16 MB
__device__ __align__(16) float  g_attn[MROWS*ND];    // 16 MB  [B*S, H*d]
__device__ __align__(16) float2 g_stats[NB*NH*NS];   // (rowmax, rowsum)

// =============================================================================
// Projection GEMM:  Y[m,n] = sum_k X[m,k] * W[n,k] + bias[n]
//   mode 0/1/2: X = q/k/v input, write to g_qh/g_kh/g_vh in [B,H,S,d] layout
//   mode 3    : X = g_attn,      write to OutP in plain [M,N] layout
// Tile: BM=128, BN=64, BK=16; 256 threads; 8x4 micro-tile per thread.
// =============================================================================
__global__ void __launch_bounds__(256)
proj_kernel(const float* __restrict__ Xp, const float* __restrict__ W,
            const float* __restrict__ bias, float* __restrict__ OutP, int mode)
{
    __shared__ __align__(16) float As[128][20];  // [row][k] pad->20 (16B-aligned rows)
    __shared__ __align__(16) float Bs[16][68];   // transposed: [k][col]

    const float* X = (mode == 3) ? g_attn : Xp;

    const int tid = threadIdx.x;
    const int tx  = tid & 15;          // 16 col-groups
    const int ty  = tid >> 4;          // 16 row-groups
    const int n0  = blockIdx.x * 64;
    const int m0  = blockIdx.y * 128;

    float acc[8][4];
    #pragma unroll
    for (int i = 0; i < 8; ++i)
        #pragma unroll
        for (int j = 0; j < 4; ++j) acc[i][j] = 0.f;

    for (int kt = 0; kt < 64; ++kt) {
        const int k0 = kt * 16;
        __syncthreads();
        // load A tile 128x16 (2 float4 per thread)
        #pragma unroll
        for (int i = 0; i < 2; ++i) {
            int e = tid + i * 256;
            int r = e >> 2, f = e & 3;
            float4 v = *(const float4*)(X + (size_t)(m0 + r) * ND + k0 + f * 4);
            *(float4*)&As[r][f * 4] = v;
        }
        // load W tile 64x16, store transposed (1 float4 per thread)
        {
            int r = tid >> 2, f = tid & 3;
            float4 v = *(const float4*)(W + (size_t)(n0 + r) * ND + k0 + f * 4);
            Bs[f * 4 + 0][r] = v.x; Bs[f * 4 + 1][r] = v.y;
            Bs[f * 4 + 2][r] = v.z; Bs[f * 4 + 3][r] = v.w;
        }
        __syncthreads();
        #pragma unroll
        for (int kk = 0; kk < 16; ++kk) {
            float b0 = Bs[kk][tx * 4 + 0], b1 = Bs[kk][tx * 4 + 1];
            float b2 = Bs[kk][tx * 4 + 2], b3 = Bs[kk][tx * 4 + 3];
            #pragma unroll
            for (int i = 0; i < 8; ++i) {
                float a = As[ty * 8 + i][kk];
                acc[i][0] += a * b0; acc[i][1] += a * b1;
                acc[i][2] += a * b2; acc[i][3] += a * b3;
            }
        }
    }

    float4 bv = *(const float4*)(bias + n0 + tx * 4);
    if (mode < 3) {
        const int h = n0 >> 6;           // BN=64 == head size -> one head per block col
        float* dstbase = (mode == 0) ? g_qh : (mode == 1) ? g_kh : g_vh;
        #pragma unroll
        for (int i = 0; i < 8; ++i) {
            int m  = m0 + ty * 8 + i;
            int bb = m >> 11;            // m / NS
            int s  = m & (NS - 1);
            float4 o;
            o.x = acc[i][0] + bv.x; o.y = acc[i][1] + bv.y;
            o.z = acc[i][2] + bv.z; o.w = acc[i][3] + bv.w;
            *(float4*)(dstbase + (size_t)((bb * NH + h) * NS + s) * DP + tx * 4) = o;
        }
    } else {
        #pragma unroll
        for (int i = 0; i < 8; ++i) {
            int m = m0 + ty * 8 + i;
            float4 o;
            o.x = acc[i][0] + bv.x; o.y = acc[i][1] + bv.y;
            o.z = acc[i][2] + bv.z; o.w = acc[i][3] + bv.w;
            *(float4*)(OutP + (size_t)m * ND + n0 + tx * 4) = o;
        }
    }
}

// =============================================================================
// Kernel 1: raw logits + online softmax stats.
//   logits = (qh . kh)/8 + mask*1e-9   -> stored RAW into the weights buffer
//   per-row running (max, sum_exp) -> g_stats
// Block: (h, qtile of 64, b); 256 threads (16x16), 4x4 micro-tile.
// =============================================================================
__global__ void __launch_bounds__(256)
logits_kernel(const float* __restrict__ mask, float* __restrict__ wbuf)
{
    __shared__ __align__(16) float qs[64][68];
    __shared__ __align__(16) float ks[64][68];

    const int tid = threadIdx.x;
    const int tx  = tid & 15, ty = tid >> 4;
    const int h = blockIdx.x, qt = blockIdx.y, b = blockIdx.z;
    const int q0 = qt * 64;

    const float* qhp = g_qh + (size_t)((b * NH + h) * NS + q0) * DP;
    const float* khp = g_kh + (size_t)((b * NH + h) * NS) * DP;
    float*       wrow = wbuf + (size_t)((b * NH + h) * NS + q0) * NS;
    const float* mrow = mask + (size_t)(b * NS + q0) * NS;

    // load q tile (natural [row][d])
    #pragma unroll
    for (int i = 0; i < 4; ++i) {
        int e = tid + i * 256;
        int r = e >> 4, f = e & 15;
        *(float4*)&qs[r][f * 4] = *(const float4*)(qhp + (size_t)r * DP + f * 4);
    }

    float mrun[4], lrun[4];
    #pragma unroll
    for (int i = 0; i < 4; ++i) { mrun[i] = -1e30f; lrun[i] = 0.f; }

    for (int kt = 0; kt < 32; ++kt) {
        const int k0 = kt * 64;
        __syncthreads();
        #pragma unroll
        for (int i = 0; i < 4; ++i) {
            int e = tid + i * 256;
            int r = e >> 4, f = e & 15;
            *(float4*)&ks[r][f * 4] = *(const float4*)(khp + (size_t)(k0 + r) * DP + f * 4);
        }
        __syncthreads();

        float s[4][4];
        #pragma unroll
        for (int i = 0; i < 4; ++i)
            #pragma unroll
            for (int j = 0; j < 4; ++j) s[i][j] = 0.f;

        #pragma unroll
        for (int d4 = 0; d4 < 16; ++d4) {
            float4 qv[4], kv[4];
            #pragma unroll
            for (int i = 0; i < 4; ++i) qv[i] = *(float4*)&qs[ty * 4 + i][d4 * 4];
            #pragma unroll
            for (int j = 0; j < 4; ++j) kv[j] = *(float4*)&ks[tx * 4 + j][d4 * 4];
            #pragma unroll
            for (int i = 0; i < 4; ++i)
                #pragma unroll
                for (int j = 0; j < 4; ++j)
                    s[i][j] += qv[i].x * kv[j].x + qv[i].y * kv[j].y
                             + qv[i].z * kv[j].z + qv[i].w * kv[j].w;
        }

        #pragma unroll
        for (int i = 0; i < 4; ++i) {
            int r = ty * 4 + i;
            float4 mv = *(const float4*)(mrow + (size_t)r * NS + k0 + tx * 4);
            float v0 = s[i][0] * 0.125f + mv.x * 1e-9f;
            float v1 = s[i][1] * 0.125f + mv.y * 1e-9f;
            float v2 = s[i][2] * 0.125f + mv.z * 1e-9f;
            float v3 = s[i][3] * 0.125f + mv.w * 1e-9f;
            float4 o = make_float4(v0, v1, v2, v3);
            *(float4*)(wrow + (size_t)r * NS + k0 + tx * 4) = o;

            float tmax = fmaxf(fmaxf(v0, v1), fmaxf(v2, v3));
            #pragma unroll
            for (int off = 1; off < 16; off <<= 1)
                tmax = fmaxf(tmax, __shfl_xor_sync(0xffffffffu, tmax, off));
            float mnew = fmaxf(mrun[i], tmax);
            float ps = __expf(v0 - mnew) + __expf(v1 - mnew)
                     + __expf(v2 - mnew) + __expf(v3 - mnew);
            #pragma unroll
            for (int off = 1; off < 16; off <<= 1)
                ps += __shfl_xor_sync(0xffffffffu, ps, off);
            lrun[i] = lrun[i] * __expf(mrun[i] - mnew) + ps;
            mrun[i] = mnew;
        }
    }

    if (tx == 0) {
        #pragma unroll
        for (int i = 0; i < 4; ++i)
            g_stats[(b * NH + h) * NS + q0 + ty * 4 + i] = make_float2(mrun[i], lrun[i]);
    }
}

// =============================================================================
// Kernel 2: softmax normalize (in place -> final weights output) fused with A.V.
//   w = exp(s - m) / l ;  attn[r,d] += w * vh[key,d]
//   attn written to g_attn in [B*S, H*d] layout for the final GEMM.
// =============================================================================
__global__ void __launch_bounds__(256)
softmax_av_kernel(float* __restrict__ wbuf)
{
    __shared__ __align__(16) float vs[64][68];   // [key][d]
    __shared__ __align__(16) float wsT[64][68];  // [key][row]

    const int tid = threadIdx.x;
    const int tx  = tid & 15, ty = tid >> 4;
    const int h = blockIdx.x, qt = blockIdx.y, b = blockIdx.z;
    const int q0 = qt * 64;

    const float* vhp = g_vh + (size_t)((b * NH + h) * NS) * DP;
    float*       wrow = wbuf + (size_t)((b * NH + h) * NS + q0) * NS;

    float mi[4], li[4];
    #pragma unroll
    for (int i = 0; i < 4; ++i) {
        float2 st = g_stats[(b * NH + h) * NS + q0 + ty * 4 + i];
        mi[i] = st.x;
        li[i] = 1.0f / st.y;
    }

    float acc[4][4];
    #pragma unroll
    for (int i = 0; i < 4; ++i)
        #pragma unroll
        for (int j = 0; j < 4; ++j) acc[i][j] = 0.f;

    for (int kt = 0; kt < 32; ++kt) {
        const int k0 = kt * 64;
        __syncthreads();
        // V tile
        #pragma unroll
        for (int i = 0; i < 4; ++i) {
            int e = tid + i * 256;
            int r = e >> 4, f = e & 15;
            *(float4*)&vs[r][f * 4] = *(const float4*)(vhp + (size_t)(k0 + r) * DP + f * 4);
        }
        // softmax transform + write final weights + stage transposed into smem
        #pragma unroll
        for (int i = 0; i < 4; ++i) {
            int r = ty * 4 + i;
            float4 sv = *(float4*)(wrow + (size_t)r * NS + k0 + tx * 4);
            float4 w;
            w.x = __expf(sv.x - mi[i]) * li[i];
            w.y = __expf(sv.y - mi[i]) * li[i];
            w.z = __expf(sv.z - mi[i]) * li[i];
            w.w = __expf(sv.w - mi[i]) * li[i];
            *(float4*)(wrow + (size_t)r * NS + k0 + tx * 4) = w;
            wsT[tx * 4 + 0][r] = w.x; wsT[tx * 4 + 1][r] = w.y;
            wsT[tx * 4 + 2][r] = w.z; wsT[tx * 4 + 3][r] = w.w;
        }
        __syncthreads();
        // attn += W_tile @ V_tile
        #pragma unroll
        for (int kk = 0; kk < 64; ++kk) {
            float4 wv = *(float4*)&wsT[kk][ty * 4];
            float4 vv = *(float4*)&vs[kk][tx * 4];
            acc[0][0] += wv.x * vv.x; acc[0][1] += wv.x * vv.y;
            acc[0][2] += wv.x * vv.z; acc[0][3] += wv.x * vv.w;
            acc[1][0] += wv.y * vv.x; acc[1][1] += wv.y * vv.y;
            acc[1][2] += wv.y * vv.z; acc[1][3] += wv.y * vv.w;
            acc[2][0] += wv.z * vv.x; acc[2][1] += wv.z * vv.y;
            acc[2][2] += wv.z * vv.z; acc[2][3] += wv.z * vv.w;
            acc[3][0] += wv.w * vv.x; acc[3][1] += wv.w * vv.y;
            acc[3][2] += wv.w * vv.z; acc[3][3] += wv.w * vv.w;
        }
    }

    #pragma unroll
    for (int i = 0; i < 4; ++i) {
        float4 o = make_float4(acc[i][0], acc[i][1], acc[i][2], acc[i][3]);
        *(float4*)(g_attn + (size_t)(b * NS + q0 + ty * 4 + i) * ND + h * DP + tx * 4) = o;
    }
}

// =============================================================================
extern "C" void kernel_launch(void* const* d_in, const int* in_sizes, int n_in,
                              void* d_out, int out_size)
{
    const float* q    = (const float*)d_in[0];
    const float* k    = (const float*)d_in[1];
    const float* v    = (const float*)d_in[2];
    const float* mask = (const float*)d_in[3];
    const float* Wq   = (const float*)d_in[4];
    const float* bq   = (const float*)d_in[5];
    const float* Wk   = (const float*)d_in[6];
    const float* bk   = (const float*)d_in[7];
    const float* Wv   = (const float*)d_in[8];
    const float* bv   = (const float*)d_in[9];
    const float* Wo   = (const float*)d_in[10];
    const float* bo   = (const float*)d_in[11];

    float* out     = (float*)d_out;                       // [B*S, D]
    float* weights = out + (size_t)MROWS * ND;            // [B,H,S,S] after `out`

    dim3 gp(ND / 64, MROWS / 128);   // (16, 32)
    proj_kernel<<<gp, 256>>>(q, Wq, bq, nullptr, 0);
    proj_kernel<<<gp, 256>>>(k, Wk, bk, nullptr, 1);
    proj_kernel<<<gp, 256>>>(v, Wv, bv, nullptr, 2);

    dim3 ga(NH, NS / 64, NB);        // (16, 32, 2)
    logits_kernel<<<ga, 256>>>(mask, weights);
    softmax_av_kernel<<<ga, 256>>>(weights);

    proj_kernel<<<gp, 256>>>(nullptr, Wo, bo, out, 3);
}

// round 4
// speedup vs baseline: 1.2399x; 1.2399x over previous
#include <cuda_runtime.h>

#define NB 2
#define NS 2048
#define ND 1024
#define NH 16
#define DP 64
#define MROWS (NB*NS)   // 4096

typedef unsigned long long u64;

// ---- packed f32x2 helpers (FFMA2 is PTX-only on sm_103a) ----------------
__device__ __forceinline__ u64 pk2(float x, float y) {
    u64 r; asm("mov.b64 %0, {%1, %2};" : "=l"(r) : "f"(x), "f"(y)); return r;
}
__device__ __forceinline__ void fma2(u64 &d, u64 a, u64 b) {
    asm("fma.rn.f32x2 %0, %1, %2, %0;" : "+l"(d) : "l"(a), "l"(b));
}
__device__ __forceinline__ float2 up2(u64 a) {
    float2 r; asm("mov.b64 {%0, %1}, %2;" : "=f"(r.x), "=f"(r.y) : "l"(a)); return r;
}

// ---------------- device scratch -----------------------------------------
__device__ __align__(16) float  g_qh[NB*NH*NS*DP];   // [B,H,S,d]
__device__ __align__(16) float  g_kh[NB*NH*NS*DP];
__device__ __align__(16) float  g_vh[NB*NH*NS*DP];
__device__ __align__(16) float  g_attn[MROWS*ND];    // [B*S, H*d]
__device__ __align__(16) float2 g_stats[NB*NH*NS];   // (rowmax, rowsum)

// =============================================================================
// Projection GEMM: Y[m,n] = sum_k X[m,k]*W[n,k] + bias[n]
// 128x128 tile, BK=16, 256 threads, 8x8 per thread (rows/cols split 4+4).
// =============================================================================
__global__ void __launch_bounds__(256)
proj_kernel(const float* __restrict__ Xp, const float* __restrict__ W,
            const float* __restrict__ bias, float* __restrict__ OutP, int mode)
{
    __shared__ __align__(16) float AsT[16][132];  // [k][m]
    __shared__ __align__(16) float BsT[16][132];  // [k][n]

    const float* X = (mode == 3) ? g_attn : Xp;

    const int tid = threadIdx.x;
    const int tx  = tid & 15;
    const int ty  = tid >> 4;
    const int n0  = blockIdx.x * 128;
    const int m0  = blockIdx.y * 128;

    u64 acc2[8][4];
    #pragma unroll
    for (int i = 0; i < 8; ++i)
        #pragma unroll
        for (int j = 0; j < 4; ++j) acc2[i][j] = 0ULL;

    for (int kt = 0; kt < 64; ++kt) {
        const int k0 = kt * 16;
        __syncthreads();
        #pragma unroll
        for (int i = 0; i < 2; ++i) {
            int e = tid + i * 256;
            int r = e >> 2, f = e & 3;
            float4 v = *(const float4*)(X + (size_t)(m0 + r) * ND + k0 + f * 4);
            AsT[f*4+0][r] = v.x; AsT[f*4+1][r] = v.y;
            AsT[f*4+2][r] = v.z; AsT[f*4+3][r] = v.w;
        }
        #pragma unroll
        for (int i = 0; i < 2; ++i) {
            int e = tid + i * 256;
            int r = e >> 2, f = e & 3;
            float4 v = *(const float4*)(W + (size_t)(n0 + r) * ND + k0 + f * 4);
            BsT[f*4+0][r] = v.x; BsT[f*4+1][r] = v.y;
            BsT[f*4+2][r] = v.z; BsT[f*4+3][r] = v.w;
        }
        __syncthreads();
        #pragma unroll
        for (int kk = 0; kk < 16; ++kk) {
            float4 a0 = *(const float4*)&AsT[kk][ty * 4];
            float4 a1 = *(const float4*)&AsT[kk][64 + ty * 4];
            ulonglong2 b0 = *(const ulonglong2*)&BsT[kk][tx * 4];
            ulonglong2 b1 = *(const ulonglong2*)&BsT[kk][64 + tx * 4];
            float av[8];
            av[0]=a0.x; av[1]=a0.y; av[2]=a0.z; av[3]=a0.w;
            av[4]=a1.x; av[5]=a1.y; av[6]=a1.z; av[7]=a1.w;
            #pragma unroll
            for (int ri = 0; ri < 8; ++ri) {
                u64 aa = pk2(av[ri], av[ri]);
                fma2(acc2[ri][0], aa, b0.x); fma2(acc2[ri][1], aa, b0.y);
                fma2(acc2[ri][2], aa, b1.x); fma2(acc2[ri][3], aa, b1.y);
            }
        }
    }

    float4 bv0 = *(const float4*)(bias + n0 + tx * 4);
    float4 bv1 = *(const float4*)(bias + n0 + 64 + tx * 4);

    #pragma unroll
    for (int ri = 0; ri < 8; ++ri) {
        int m = m0 + ((ri < 4) ? (ty * 4 + ri) : (64 + ty * 4 + (ri - 4)));
        float2 p0 = up2(acc2[ri][0]), p1 = up2(acc2[ri][1]);
        float2 p2 = up2(acc2[ri][2]), p3 = up2(acc2[ri][3]);
        float4 o0 = make_float4(p0.x + bv0.x, p0.y + bv0.y, p1.x + bv0.z, p1.y + bv0.w);
        float4 o1 = make_float4(p2.x + bv1.x, p2.y + bv1.y, p3.x + bv1.z, p3.y + bv1.w);
        if (mode < 3) {
            float* dstbase = (mode == 0) ? g_qh : (mode == 1) ? g_kh : g_vh;
            int bb = m >> 11;
            int s  = m & (NS - 1);
            int h0 = n0 >> 6;
            *(float4*)(dstbase + (size_t)((bb * NH + h0    ) * NS + s) * DP + tx * 4) = o0;
            *(float4*)(dstbase + (size_t)((bb * NH + h0 + 1) * NS + s) * DP + tx * 4) = o1;
        } else {
            *(float4*)(OutP + (size_t)m * ND + n0 + tx * 4) = o0;
            *(float4*)(OutP + (size_t)m * ND + n0 + 64 + tx * 4) = o1;
        }
    }
}

// =============================================================================
// Logits: raw (qk/8 + mask*1e-9) into weights buffer + online (max,sum) stats.
// Tile 128q x 128k per block, d in 2 chunks of 32. 8x8 per thread.
// =============================================================================
__global__ void __launch_bounds__(256)
logits_kernel(const float* __restrict__ mask, float* __restrict__ wbuf)
{
    __shared__ __align__(16) float qs [128][36];  // [q][d-chunk]
    __shared__ __align__(16) float ksT[32][132];  // [d-chunk][key]

    const int tid = threadIdx.x;
    const int tx  = tid & 15, ty = tid >> 4;
    const int h = blockIdx.x, qt = blockIdx.y, b = blockIdx.z;
    const int q0 = qt * 128;

    const float* qhp = g_qh + (size_t)((b * NH + h) * NS + q0) * DP;
    const float* khp = g_kh + (size_t)((b * NH + h) * NS) * DP;
    float*       wrow = wbuf + (size_t)((b * NH + h) * NS + q0) * NS;
    const float* mrow = mask + (size_t)(b * NS + q0) * NS;

    float mrun[8], lrun[8];
    #pragma unroll
    for (int i = 0; i < 8; ++i) { mrun[i] = -1e30f; lrun[i] = 0.f; }

    for (int kt = 0; kt < 16; ++kt) {
        const int k0 = kt * 128;

        u64 s2[8][4];
        #pragma unroll
        for (int i = 0; i < 8; ++i)
            #pragma unroll
            for (int j = 0; j < 4; ++j) s2[i][j] = 0ULL;

        for (int dc = 0; dc < 2; ++dc) {
            const int d0 = dc * 32;
            __syncthreads();
            #pragma unroll
            for (int i = 0; i < 4; ++i) {
                int e = tid + i * 256;
                int r = e >> 3, f = e & 7;
                *(float4*)&qs[r][f * 4] =
                    *(const float4*)(qhp + (size_t)r * DP + d0 + f * 4);
            }
            #pragma unroll
            for (int i = 0; i < 4; ++i) {
                int e = tid + i * 256;
                int r = e >> 3, f = e & 7;
                float4 v = *(const float4*)(khp + (size_t)(k0 + r) * DP + d0 + f * 4);
                ksT[f*4+0][r] = v.x; ksT[f*4+1][r] = v.y;
                ksT[f*4+2][r] = v.z; ksT[f*4+3][r] = v.w;
            }
            __syncthreads();

            #pragma unroll
            for (int d4 = 0; d4 < 8; ++d4) {
                float4 qv[8];
                #pragma unroll
                for (int i = 0; i < 8; ++i)
                    qv[i] = *(const float4*)&qs[ty * 8 + i][d4 * 4];
                #pragma unroll
                for (int c = 0; c < 4; ++c) {
                    int dd = d4 * 4 + c;
                    ulonglong2 k0v = *(const ulonglong2*)&ksT[dd][tx * 4];
                    ulonglong2 k1v = *(const ulonglong2*)&ksT[dd][64 + tx * 4];
                    #pragma unroll
                    for (int i = 0; i < 8; ++i) {
                        float qc = (c == 0) ? qv[i].x : (c == 1) ? qv[i].y
                                 : (c == 2) ? qv[i].z : qv[i].w;
                        u64 aa = pk2(qc, qc);
                        fma2(s2[i][0], aa, k0v.x); fma2(s2[i][1], aa, k0v.y);
                        fma2(s2[i][2], aa, k1v.x); fma2(s2[i][3], aa, k1v.y);
                    }
                }
            }
        }

        // epilogue for this key tile: scale, mask, write raw, update stats
        #pragma unroll
        for (int i = 0; i < 8; ++i) {
            int r = ty * 8 + i;
            float2 p0 = up2(s2[i][0]), p1 = up2(s2[i][1]);
            float2 p2 = up2(s2[i][2]), p3 = up2(s2[i][3]);
            float4 mv0 = *(const float4*)(mrow + (size_t)r * NS + k0 + tx * 4);
            float4 mv1 = *(const float4*)(mrow + (size_t)r * NS + k0 + 64 + tx * 4);
            float v0 = p0.x * 0.125f + mv0.x * 1e-9f;
            float v1 = p0.y * 0.125f + mv0.y * 1e-9f;
            float v2 = p1.x * 0.125f + mv0.z * 1e-9f;
            float v3 = p1.y * 0.125f + mv0.w * 1e-9f;
            float v4 = p2.x * 0.125f + mv1.x * 1e-9f;
            float v5 = p2.y * 0.125f + mv1.y * 1e-9f;
            float v6 = p3.x * 0.125f + mv1.z * 1e-9f;
            float v7 = p3.y * 0.125f + mv1.w * 1e-9f;
            *(float4*)(wrow + (size_t)r * NS + k0 + tx * 4)      = make_float4(v0, v1, v2, v3);
            *(float4*)(wrow + (size_t)r * NS + k0 + 64 + tx * 4) = make_float4(v4, v5, v6, v7);

            float tmax = fmaxf(fmaxf(fmaxf(v0, v1), fmaxf(v2, v3)),
                               fmaxf(fmaxf(v4, v5), fmaxf(v6, v7)));
            #pragma unroll
            for (int off = 1; off < 16; off <<= 1)
                tmax = fmaxf(tmax, __shfl_xor_sync(0xffffffffu, tmax, off));
            float mnew = fmaxf(mrun[i], tmax);
            float ps = __expf(v0 - mnew) + __expf(v1 - mnew)
                     + __expf(v2 - mnew) + __expf(v3 - mnew)
                     + __expf(v4 - mnew) + __expf(v5 - mnew)
                     + __expf(v6 - mnew) + __expf(v7 - mnew);
            #pragma unroll
            for (int off = 1; off < 16; off <<= 1)
                ps += __shfl_xor_sync(0xffffffffu, ps, off);
            lrun[i] = lrun[i] * __expf(mrun[i] - mnew) + ps;
            mrun[i] = mnew;
        }
    }

    if (tx == 0) {
        #pragma unroll
        for (int i = 0; i < 8; ++i)
            g_stats[(b * NH + h) * NS + q0 + ty * 8 + i] = make_float2(mrun[i], lrun[i]);
    }
}

// =============================================================================
// Softmax normalize (in place -> weights output) fused with A.V.
// Tile 128q x 64d, keys in chunks of 64. V in smem; normalized w re-read via
// L2-hot broadcast LDG (no smem w tile).
// =============================================================================
__global__ void __launch_bounds__(256)
softmax_av_kernel(float* __restrict__ wbuf)
{
    __shared__ __align__(16) float vs[64][68];   // [key][d]

    const int tid = threadIdx.x;
    const int tx  = tid & 15, ty = tid >> 4;
    const int h = blockIdx.x, qt = blockIdx.y, b = blockIdx.z;
    const int q0 = qt * 128;

    const float* vhp = g_vh + (size_t)((b * NH + h) * NS) * DP;
    float*       wrow = wbuf + (size_t)((b * NH + h) * NS + q0) * NS;

    float mi[8], li[8];
    #pragma unroll
    for (int i = 0; i < 8; ++i) {
        float2 st = g_stats[(b * NH + h) * NS + q0 + ty * 8 + i];
        mi[i] = st.x;
        li[i] = 1.0f / st.y;
    }

    u64 acc2[8][2];
    #pragma unroll
    for (int i = 0; i < 8; ++i) { acc2[i][0] = 0ULL; acc2[i][1] = 0ULL; }

    for (int kt = 0; kt < 32; ++kt) {
        const int k0 = kt * 64;
        __syncthreads();
        #pragma unroll
        for (int i = 0; i < 4; ++i) {
            int e = tid + i * 256;
            int r = e >> 4, f = e & 15;
            *(float4*)&vs[r][f * 4] =
                *(const float4*)(vhp + (size_t)(k0 + r) * DP + f * 4);
        }
        // normalize this block's 128x64 chunk of weights in place
        #pragma unroll
        for (int i = 0; i < 8; ++i) {
            int r = ty * 8 + i;
            float4 sv = *(float4*)(wrow + (size_t)r * NS + k0 + tx * 4);
            float4 w;
            w.x = __expf(sv.x - mi[i]) * li[i];
            w.y = __expf(sv.y - mi[i]) * li[i];
            w.z = __expf(sv.z - mi[i]) * li[i];
            w.w = __expf(sv.w - mi[i]) * li[i];
            *(float4*)(wrow + (size_t)r * NS + k0 + tx * 4) = w;
        }
        __syncthreads();
        // attn += W_chunk @ V_chunk  (w via broadcast LDG, v via smem pairs)
        #pragma unroll 8
        for (int kk = 0; kk < 64; ++kk) {
            ulonglong2 vv = *(const ulonglong2*)&vs[kk][tx * 4];
            #pragma unroll
            for (int i = 0; i < 8; ++i) {
                float w = wrow[(size_t)(ty * 8 + i) * NS + k0 + kk];
                u64 aa = pk2(w, w);
                fma2(acc2[i][0], aa, vv.x);
                fma2(acc2[i][1], aa, vv.y);
            }
        }
    }

    #pragma unroll
    for (int i = 0; i < 8; ++i) {
        float2 p0 = up2(acc2[i][0]), p1 = up2(acc2[i][1]);
        float4 o = make_float4(p0.x, p0.y, p1.x, p1.y);
        *(float4*)(g_attn + (size_t)(b * NS + q0 + ty * 8 + i) * ND + h * DP + tx * 4) = o;
    }
}

// =============================================================================
extern "C" void kernel_launch(void* const* d_in, const int* in_sizes, int n_in,
                              void* d_out, int out_size)
{
    const float* q    = (const float*)d_in[0];
    const float* k    = (const float*)d_in[1];
    const float* v    = (const float*)d_in[2];
    const float* mask = (const float*)d_in[3];
    const float* Wq   = (const float*)d_in[4];
    const float* bq   = (const float*)d_in[5];
    const float* Wk   = (const float*)d_in[6];
    const float* bk   = (const float*)d_in[7];
    const float* Wv   = (const float*)d_in[8];
    const float* bv   = (const float*)d_in[9];
    const float* Wo   = (const float*)d_in[10];
    const float* bo   = (const float*)d_in[11];

    float* out     = (float*)d_out;
    float* weights = out + (size_t)MROWS * ND;

    dim3 gp(ND / 128, MROWS / 128);   // (8, 32)
    proj_kernel<<<gp, 256>>>(q, Wq, bq, nullptr, 0);
    proj_kernel<<<gp, 256>>>(k, Wk, bk, nullptr, 1);
    proj_kernel<<<gp, 256>>>(v, Wv, bv, nullptr, 2);

    dim3 ga(NH, NS / 128, NB);        // (16, 16, 2)
    logits_kernel<<<ga, 256>>>(mask, weights);
    softmax_av_kernel<<<ga, 256>>>(weights);

    proj_kernel<<<gp, 256>>>(nullptr, Wo, bo, out, 3);
}

// round 7
// speedup vs baseline: 1.2413x; 1.0012x over previous
#include <cuda_runtime.h>

#define NB 2
#define NS 2048
#define ND 1024
#define NH 16
#define DP 64
#define MROWS (NB*NS)   // 4096

typedef unsigned long long u64;

// ---- packed f32x2 helpers (FFMA2 is PTX-only on sm_103a) ----------------
__device__ __forceinline__ u64 pk2(float x, float y) {
    u64 r; asm("mov.b64 %0, {%1, %2};" : "=l"(r) : "f"(x), "f"(y)); return r;
}
__device__ __forceinline__ void fma2(u64 &d, u64 a, u64 b) {
    asm("fma.rn.f32x2 %0, %1, %2, %0;" : "+l"(d) : "l"(a), "l"(b));
}
__device__ __forceinline__ float2 up2(u64 a) {
    float2 r; asm("mov.b64 {%0, %1}, %2;" : "=f"(r.x), "=f"(r.y) : "l"(a)); return r;
}

// ---------------- device scratch -----------------------------------------
__device__ __align__(16) float  g_qh[NB*NH*NS*DP];   // [B,H,S,d]
__device__ __align__(16) float  g_kh[NB*NH*NS*DP];
__device__ __align__(16) float  g_vh[NB*NH*NS*DP];
__device__ __align__(16) float  g_attn[MROWS*ND];    // [B*S, H*d]
__device__ __align__(16) float2 g_stats[NB*NH*NS];   // (rowmax, rowsum)

// =============================================================================
// Projection GEMM: Y[m,n] = sum_k X[m,k]*W[n,k] + bias[n]
// 128x128 tile, BK=16, 256 threads, 8x8 per thread (rows/cols split 4+4).
// =============================================================================
__global__ void __launch_bounds__(256)
proj_kernel(const float* __restrict__ Xp, const float* __restrict__ W,
            const float* __restrict__ bias, float* __restrict__ OutP, int mode)
{
    __shared__ __align__(16) float AsT[16][132];  // [k][m]
    __shared__ __align__(16) float BsT[16][132];  // [k][n]

    const float* X = (mode == 3) ? g_attn : Xp;

    const int tid = threadIdx.x;
    const int tx  = tid & 15;
    const int ty  = tid >> 4;
    const int n0  = blockIdx.x * 128;
    const int m0  = blockIdx.y * 128;

    u64 acc2[8][4];
    #pragma unroll
    for (int i = 0; i < 8; ++i)
        #pragma unroll
        for (int j = 0; j < 4; ++j) acc2[i][j] = 0ULL;

    for (int kt = 0; kt < 64; ++kt) {
        const int k0 = kt * 16;
        __syncthreads();
        #pragma unroll
        for (int i = 0; i < 2; ++i) {
            int e = tid + i * 256;
            int r = e >> 2, f = e & 3;
            float4 v = *(const float4*)(X + (size_t)(m0 + r) * ND + k0 + f * 4);
            AsT[f*4+0][r] = v.x; AsT[f*4+1][r] = v.y;
            AsT[f*4+2][r] = v.z; AsT[f*4+3][r] = v.w;
        }
        #pragma unroll
        for (int i = 0; i < 2; ++i) {
            int e = tid + i * 256;
            int r = e >> 2, f = e & 3;
            float4 v = *(const float4*)(W + (size_t)(n0 + r) * ND + k0 + f * 4);
            BsT[f*4+0][r] = v.x; BsT[f*4+1][r] = v.y;
            BsT[f*4+2][r] = v.z; BsT[f*4+3][r] = v.w;
        }
        __syncthreads();
        #pragma unroll
        for (int kk = 0; kk < 16; ++kk) {
            float4 a0 = *(const float4*)&AsT[kk][ty * 4];
            float4 a1 = *(const float4*)&AsT[kk][64 + ty * 4];
            ulonglong2 b0 = *(const ulonglong2*)&BsT[kk][tx * 4];
            ulonglong2 b1 = *(const ulonglong2*)&BsT[kk][64 + tx * 4];
            float av[8];
            av[0]=a0.x; av[1]=a0.y; av[2]=a0.z; av[3]=a0.w;
            av[4]=a1.x; av[5]=a1.y; av[6]=a1.z; av[7]=a1.w;
            #pragma unroll
            for (int ri = 0; ri < 8; ++ri) {
                u64 aa = pk2(av[ri], av[ri]);
                fma2(acc2[ri][0], aa, b0.x); fma2(acc2[ri][1], aa, b0.y);
                fma2(acc2[ri][2], aa, b1.x); fma2(acc2[ri][3], aa, b1.y);
            }
        }
    }

    float4 bv0 = *(const float4*)(bias + n0 + tx * 4);
    float4 bv1 = *(const float4*)(bias + n0 + 64 + tx * 4);

    #pragma unroll
    for (int ri = 0; ri < 8; ++ri) {
        int m = m0 + ((ri < 4) ? (ty * 4 + ri) : (64 + ty * 4 + (ri - 4)));
        float2 p0 = up2(acc2[ri][0]), p1 = up2(acc2[ri][1]);
        float2 p2 = up2(acc2[ri][2]), p3 = up2(acc2[ri][3]);
        float4 o0 = make_float4(p0.x + bv0.x, p0.y + bv0.y, p1.x + bv0.z, p1.y + bv0.w);
        float4 o1 = make_float4(p2.x + bv1.x, p2.y + bv1.y, p3.x + bv1.z, p3.y + bv1.w);
        if (mode < 3) {
            float* dstbase = (mode == 0) ? g_qh : (mode == 1) ? g_kh : g_vh;
            int bb = m >> 11;
            int s  = m & (NS - 1);
            int h0 = n0 >> 6;
            *(float4*)(dstbase + (size_t)((bb * NH + h0    ) * NS + s) * DP + tx * 4) = o0;
            *(float4*)(dstbase + (size_t)((bb * NH + h0 + 1) * NS + s) * DP + tx * 4) = o1;
        } else {
            *(float4*)(OutP + (size_t)m * ND + n0 + tx * 4) = o0;
            *(float4*)(OutP + (size_t)m * ND + n0 + 64 + tx * 4) = o1;
        }
    }
}

// =============================================================================
// Logits: raw (qk/8 + mask*1e-9) into weights buffer + online (max,sum) stats.
// Tile 128q x 128k per block, d in 2 chunks of 32. 8x8 per thread.
// =============================================================================
__global__ void __launch_bounds__(256)
logits_kernel(const float* __restrict__ mask, float* __restrict__ wbuf)
{
    __shared__ __align__(16) float qs [128][36];  // [q][d-chunk]
    __shared__ __align__(16) float ksT[32][132];  // [d-chunk][key]

    const int tid = threadIdx.x;
    const int tx  = tid & 15, ty = tid >> 4;
    const int h = blockIdx.x, qt = blockIdx.y, b = blockIdx.z;
    const int q0 = qt * 128;

    const float* qhp = g_qh + (size_t)((b * NH + h) * NS + q0) * DP;
    const float* khp = g_kh + (size_t)((b * NH + h) * NS) * DP;
    float*       wrow = wbuf + (size_t)((b * NH + h) * NS + q0) * NS;
    const float* mrow = mask + (size_t)(b * NS + q0) * NS;

    float mrun[8], lrun[8];
    #pragma unroll
    for (int i = 0; i < 8; ++i) { mrun[i] = -1e30f; lrun[i] = 0.f; }

    for (int kt = 0; kt < 16; ++kt) {
        const int k0 = kt * 128;

        u64 s2[8][4];
        #pragma unroll
        for (int i = 0; i < 8; ++i)
            #pragma unroll
            for (int j = 0; j < 4; ++j) s2[i][j] = 0ULL;

        for (int dc = 0; dc < 2; ++dc) {
            const int d0 = dc * 32;
            __syncthreads();
            #pragma unroll
            for (int i = 0; i < 4; ++i) {
                int e = tid + i * 256;
                int r = e >> 3, f = e & 7;
                *(float4*)&qs[r][f * 4] =
                    *(const float4*)(qhp + (size_t)r * DP + d0 + f * 4);
            }
            #pragma unroll
            for (int i = 0; i < 4; ++i) {
                int e = tid + i * 256;
                int r = e >> 3, f = e & 7;
                float4 v = *(const float4*)(khp + (size_t)(k0 + r) * DP + d0 + f * 4);
                ksT[f*4+0][r] = v.x; ksT[f*4+1][r] = v.y;
                ksT[f*4+2][r] = v.z; ksT[f*4+3][r] = v.w;
            }
            __syncthreads();

            #pragma unroll
            for (int d4 = 0; d4 < 8; ++d4) {
                float4 qv[8];
                #pragma unroll
                for (int i = 0; i < 8; ++i)
                    qv[i] = *(const float4*)&qs[ty * 8 + i][d4 * 4];
                #pragma unroll
                for (int c = 0; c < 4; ++c) {
                    int dd = d4 * 4 + c;
                    ulonglong2 k0v = *(const ulonglong2*)&ksT[dd][tx * 4];
                    ulonglong2 k1v = *(const ulonglong2*)&ksT[dd][64 + tx * 4];
                    #pragma unroll
                    for (int i = 0; i < 8; ++i) {
                        float qc = (c == 0) ? qv[i].x : (c == 1) ? qv[i].y
                                 : (c == 2) ? qv[i].z : qv[i].w;
                        u64 aa = pk2(qc, qc);
                        fma2(s2[i][0], aa, k0v.x); fma2(s2[i][1], aa, k0v.y);
                        fma2(s2[i][2], aa, k1v.x); fma2(s2[i][3], aa, k1v.y);
                    }
                }
            }
        }

        // epilogue for this key tile: scale, mask, write raw, update stats
        #pragma unroll
        for (int i = 0; i < 8; ++i) {
            int r = ty * 8 + i;
            float2 p0 = up2(s2[i][0]), p1 = up2(s2[i][1]);
            float2 p2 = up2(s2[i][2]), p3 = up2(s2[i][3]);
            float4 mv0 = *(const float4*)(mrow + (size_t)r * NS + k0 + tx * 4);
            float4 mv1 = *(const float4*)(mrow + (size_t)r * NS + k0 + 64 + tx * 4);
            float v0 = p0.x * 0.125f + mv0.x * 1e-9f;
            float v1 = p0.y * 0.125f + mv0.y * 1e-9f;
            float v2 = p1.x * 0.125f + mv0.z * 1e-9f;
            float v3 = p1.y * 0.125f + mv0.w * 1e-9f;
            float v4 = p2.x * 0.125f + mv1.x * 1e-9f;
            float v5 = p2.y * 0.125f + mv1.y * 1e-9f;
            float v6 = p3.x * 0.125f + mv1.z * 1e-9f;
            float v7 = p3.y * 0.125f + mv1.w * 1e-9f;
            *(float4*)(wrow + (size_t)r * NS + k0 + tx * 4)      = make_float4(v0, v1, v2, v3);
            *(float4*)(wrow + (size_t)r * NS + k0 + 64 + tx * 4) = make_float4(v4, v5, v6, v7);

            float tmax = fmaxf(fmaxf(fmaxf(v0, v1), fmaxf(v2, v3)),
                               fmaxf(fmaxf(v4, v5), fmaxf(v6, v7)));
            #pragma unroll
            for (int off = 1; off < 16; off <<= 1)
                tmax = fmaxf(tmax, __shfl_xor_sync(0xffffffffu, tmax, off));
            float mnew = fmaxf(mrun[i], tmax);
            float ps = __expf(v0 - mnew) + __expf(v1 - mnew)
                     + __expf(v2 - mnew) + __expf(v3 - mnew)
                     + __expf(v4 - mnew) + __expf(v5 - mnew)
                     + __expf(v6 - mnew) + __expf(v7 - mnew);
            #pragma unroll
            for (int off = 1; off < 16; off <<= 1)
                ps += __shfl_xor_sync(0xffffffffu, ps, off);
            lrun[i] = lrun[i] * __expf(mrun[i] - mnew) + ps;
            mrun[i] = mnew;
        }
    }

    if (tx == 0) {
        #pragma unroll
        for (int i = 0; i < 8; ++i)
            g_stats[(b * NH + h) * NS + q0 + ty * 8 + i] = make_float2(mrun[i], lrun[i]);
    }
}

// =============================================================================
// Softmax normalize (in place -> weights output) fused with A.V.
// Tile 128q x 64d, keys in chunks of 64. V in smem; normalized w re-read via
// L2-hot broadcast LDG (no smem w tile).
// =============================================================================
__global__ void __launch_bounds__(256)
softmax_av_kernel(float* __restrict__ wbuf)
{
    __shared__ __align__(16) float vs[64][68];   // [key][d]

    const int tid = threadIdx.x;
    const int tx  = tid & 15, ty = tid >> 4;
    const int h = blockIdx.x, qt = blockIdx.y, b = blockIdx.z;
    const int q0 = qt * 128;

    const float* vhp = g_vh + (size_t)((b * NH + h) * NS) * DP;
    float*       wrow = wbuf + (size_t)((b * NH + h) * NS + q0) * NS;

    float mi[8], li[8];
    #pragma unroll
    for (int i = 0; i < 8; ++i) {
        float2 st = g_stats[(b * NH + h) * NS + q0 + ty * 8 + i];
        mi[i] = st.x;
        li[i] = 1.0f / st.y;
    }

    u64 acc2[8][2];
    #pragma unroll
    for (int i = 0; i < 8; ++i) { acc2[i][0] = 0ULL; acc2[i][1] = 0ULL; }

    for (int kt = 0; kt < 32; ++kt) {
        const int k0 = kt * 64;
        __syncthreads();
        #pragma unroll
        for (int i = 0; i < 4; ++i) {
            int e = tid + i * 256;
            int r = e >> 4, f = e & 15;
            *(float4*)&vs[r][f * 4] =
                *(const float4*)(vhp + (size_t)(k0 + r) * DP + f * 4);
        }
        // normalize this block's 128x64 chunk of weights in place
        #pragma unroll
        for (int i = 0; i < 8; ++i) {
            int r = ty * 8 + i;
            float4 sv = *(float4*)(wrow + (size_t)r * NS + k0 + tx * 4);
            float4 w;
            w.x = __expf(sv.x - mi[i]) * li[i];
            w.y = __expf(sv.y - mi[i]) * li[i];
            w.z = __expf(sv.z - mi[i]) * li[i];
            w.w = __expf(sv.w - mi[i]) * li[i];
            *(float4*)(wrow + (size_t)r * NS + k0 + tx * 4) = w;
        }
        __syncthreads();
        // attn += W_chunk @ V_chunk  (w via broadcast LDG, v via smem pairs)
        #pragma unroll 8
        for (int kk = 0; kk < 64; ++kk) {
            ulonglong2 vv = *(const ulonglong2*)&vs[kk][tx * 4];
            #pragma unroll
            for (int i = 0; i < 8; ++i) {
                float w = wrow[(size_t)(ty * 8 + i) * NS + k0 + kk];
                u64 aa = pk2(w, w);
                fma2(acc2[i][0], aa, vv.x);
                fma2(acc2[i][1], aa, vv.y);
            }
        }
    }

    #pragma unroll
    for (int i = 0; i < 8; ++i) {
        float2 p0 = up2(acc2[i][0]), p1 = up2(acc2[i][1]);
        float4 o = make_float4(p0.x, p0.y, p1.x, p1.y);
        *(float4*)(g_attn + (size_t)(b * NS + q0 + ty * 8 + i) * ND + h * DP + tx * 4) = o;
    }
}

// =============================================================================
extern "C" void kernel_launch(void* const* d_in, const int* in_sizes, int n_in,
                              void* d_out, int out_size)
{
    const float* q    = (const float*)d_in[0];
    const float* k    = (const float*)d_in[1];
    const float* v    = (const float*)d_in[2];
    const float* mask = (const float*)d_in[3];
    const float* Wq   = (const float*)d_in[4];
    const float* bq   = (const float*)d_in[5];
    const float* Wk   = (const float*)d_in[6];
    const float* bk   = (const float*)d_in[7];
    const float* Wv   = (const float*)d_in[8];
    const float* bv   = (const float*)d_in[9];
    const float* Wo   = (const float*)d_in[10];
    const float* bo   = (const float*)d_in[11];

    float* out     = (float*)d_out;
    float* weights = out + (size_t)MROWS * ND;

    dim3 gp(ND / 128, MROWS / 128);   // (8, 32)
    proj_kernel<<<gp, 256>>>(q, Wq, bq, nullptr, 0);
    proj_kernel<<<gp, 256>>>(k, Wk, bk, nullptr, 1);
    proj_kernel<<<gp, 256>>>(v, Wv, bv, nullptr, 2);

    dim3 ga(NH, NS / 128, NB);        // (16, 16, 2)
    logits_kernel<<<ga, 256>>>(mask, weights);
    softmax_av_kernel<<<ga, 256>>>(weights);

    proj_kernel<<<gp, 256>>>(nullptr, Wo, bo, out, 3);
}

// round 9
// speedup vs baseline: 2.3052x; 1.8570x over previous
#include <cuda_runtime.h>
#include <cuda_bf16.h>

#define NB 2
#define NS 2048
#define ND 1024
#define NH 16
#define DP 64
#define MROWS (NB*NS)
#define PIT 72

typedef unsigned int   u32;
typedef unsigned short u16;

__device__ __align__(16) u16   g_qhi[NB*NH*NS*DP];
__device__ __align__(16) u16   g_qlo[NB*NH*NS*DP];
__device__ __align__(16) u16   g_khi[NB*NH*NS*DP];
__device__ __align__(16) u16   g_klo[NB*NH*NS*DP];
__device__ __align__(16) u16   g_vhi[NB*NH*NS*DP];
__device__ __align__(16) u16   g_vlo[NB*NH*NS*DP];
__device__ __align__(16) float g_attn[MROWS*ND];

__device__ __forceinline__ void split1(float x, u16 &h, u16 &l) {
    __nv_bfloat16 hb = __float2bfloat16(x);
    h = __bfloat16_as_ushort(hb);
    l = __bfloat16_as_ushort(__float2bfloat16(x - __bfloat162float(hb)));
}
__device__ __forceinline__ u32 pck(u16 a, u16 b) { return (u32)a | ((u32)b << 16); }

__device__ __forceinline__ void mma_bf16(float* d, const u32* a, const u32* b) {
    asm volatile("mma.sync.aligned.m16n8k16.row.col.f32.bf16.bf16.f32 "
        "{%0,%1,%2,%3}, {%4,%5,%6,%7}, {%8,%9}, {%0,%1,%2,%3};"
        : "+f"(d[0]), "+f"(d[1]), "+f"(d[2]), "+f"(d[3])
        : "r"(a[0]), "r"(a[1]), "r"(a[2]), "r"(a[3]), "r"(b[0]), "r"(b[1]));
}
// A fragment from row-major [m][k] smem (pitch PIT u16)
__device__ __forceinline__ void lda(u32* a, const u16* S, int row, int k, int g, int t2) {
    const u16* p = S + (row + g) * PIT + k + t2;
    a[0] = *(const u32*)p;
    a[1] = *(const u32*)(p + 8 * PIT);
    a[2] = *(const u32*)(p + 8);
    a[3] = *(const u32*)(p + 8 * PIT + 8);
}
// B fragment from [n][k] smem (k contiguous)
__device__ __forceinline__ void ldb(u32* bf, const u16* S, int n, int k, int g, int t2) {
    const u16* p = S + (n + g) * PIT + k + t2;
    bf[0] = *(const u32*)p;
    bf[1] = *(const u32*)(p + 8);
}
__device__ __forceinline__ void split_st(u16* H, u16* L, int idx, float4 v) {
    u16 h0,l0,h1,l1,h2,l2,h3,l3;
    split1(v.x,h0,l0); split1(v.y,h1,l1); split1(v.z,h2,l2); split1(v.w,h3,l3);
    *(uint2*)(H + idx) = make_uint2(pck(h0,h1), pck(h2,h3));
    *(uint2*)(L + idx) = make_uint2(pck(l0,l1), pck(l2,l3));
}

// =============================================================================
// Projection GEMM: Y[m,n] = sum_k X[m,k]*W[n,k] + b[n].
// 128x128 tile, 256 thr, warp grid 2m x 4n (warp 64x32). K chunks of 64.
// modes 0/1/2 -> split bf16 heads; mode 3 -> f32 OutP.
// =============================================================================
#define PSM 73728
__global__ void __launch_bounds__(256)
proj_mma(const float* __restrict__ Xp, const float* __restrict__ W,
         const float* __restrict__ bias, float* __restrict__ OutP, int mode)
{
    extern __shared__ u16 sp[];
    u16 *AH = sp, *AL = sp + 9216, *BH = sp + 18432, *BL = sp + 27648;
    const float* X = (mode == 3) ? g_attn : Xp;
    const int tid = threadIdx.x, w = tid >> 5, lane = tid & 31;
    const int g = lane >> 2, t2 = (lane & 3) * 2;
    const int wm = w >> 2, wn = w & 3;
    const int n0 = blockIdx.x * 128, m0 = blockIdx.y * 128;

    float dd[4][4][4];
    #pragma unroll
    for (int i = 0; i < 4; ++i)
        #pragma unroll
        for (int j = 0; j < 4; ++j)
            #pragma unroll
            for (int c = 0; c < 4; ++c) dd[i][j][c] = 0.f;

    for (int kt = 0; kt < 16; ++kt) {
        const int k0 = kt * 64;
        __syncthreads();
        #pragma unroll
        for (int it = 0; it < 8; ++it) {
            int e = it * 256 + tid, r = e >> 4, c4 = (e & 15) * 4;
            float4 xv = *(const float4*)(X + (size_t)(m0 + r) * ND + k0 + c4);
            split_st(AH, AL, r * PIT + c4, xv);
            float4 wv = *(const float4*)(W + (size_t)(n0 + r) * ND + k0 + c4);
            split_st(BH, BL, r * PIT + c4, wv);
        }
        __syncthreads();
        #pragma unroll
        for (int ks = 0; ks < 4; ++ks) {
            const int kk = ks * 16;
            u32 ah[4][4], al[4][4], bh[4][2], bl[4][2];
            #pragma unroll
            for (int mt = 0; mt < 4; ++mt) {
                lda(ah[mt], AH, wm*64 + mt*16, kk, g, t2);
                lda(al[mt], AL, wm*64 + mt*16, kk, g, t2);
            }
            #pragma unroll
            for (int nt = 0; nt < 4; ++nt) {
                ldb(bh[nt], BH, wn*32 + nt*8, kk, g, t2);
                ldb(bl[nt], BL, wn*32 + nt*8, kk, g, t2);
            }
            #pragma unroll
            for (int mt = 0; mt < 4; ++mt)
                #pragma unroll
                for (int nt = 0; nt < 4; ++nt) {
                    mma_bf16(dd[mt][nt], ah[mt], bh[nt]);
                    mma_bf16(dd[mt][nt], ah[mt], bl[nt]);
                    mma_bf16(dd[mt][nt], al[mt], bh[nt]);
                }
        }
    }

    #pragma unroll
    for (int mt = 0; mt < 4; ++mt) {
        int r1 = m0 + wm*64 + mt*16 + g, r2 = r1 + 8;
        #pragma unroll
        for (int nt = 0; nt < 4; ++nt) {
            int c = n0 + wn*32 + nt*8 + t2;
            float2 bv = *(const float2*)(bias + c);
            float x0 = dd[mt][nt][0] + bv.x, x1 = dd[mt][nt][1] + bv.y;
            float x2 = dd[mt][nt][2] + bv.x, x3 = dd[mt][nt][3] + bv.y;
            if (mode < 3) {
                u16* dh = (mode == 0) ? g_qhi : (mode == 1) ? g_khi : g_vhi;
                u16* dl = (mode == 0) ? g_qlo : (mode == 1) ? g_klo : g_vlo;
                int hh = c >> 6, cd = c & 63;
                size_t i1 = ((size_t)((r1 >> 11) * NH + hh) * NS + (r1 & 2047)) * DP + cd;
                size_t i2 = ((size_t)((r2 >> 11) * NH + hh) * NS + (r2 & 2047)) * DP + cd;
                u16 h0,l0,h1,l1;
                split1(x0,h0,l0); split1(x1,h1,l1);
                *(u32*)(dh + i1) = pck(h0,h1); *(u32*)(dl + i1) = pck(l0,l1);
                split1(x2,h0,l0); split1(x3,h1,l1);
                *(u32*)(dh + i2) = pck(h0,h1); *(u32*)(dl + i2) = pck(l0,l1);
            } else {
                *(float2*)(OutP + (size_t)r1 * ND + c) = make_float2(x0, x1);
                *(float2*)(OutP + (size_t)r2 * ND + c) = make_float2(x2, x3);
            }
        }
    }
}

// =============================================================================
// Fused attention per (b,h,128 q):
// phase 1: QK^T/8 -> raw logits (wbuf) + online (max,sum) in smem.
// phase 2: normalize in place (weights output), W.V in registers -> g_attn.
// =============================================================================
#define ASMB 97280
__global__ void __launch_bounds__(256)
attn_mma(float* __restrict__ wbuf)
{
    extern __shared__ u16 sp[];
    u16 *QH = sp, *QL = sp + 9216, *KH = sp + 18432, *KL = sp + 27648;
    u16 *VH = sp + 36864, *VL = sp + 41472;
    float* fs   = (float*)(sp + 46080);
    float* mrun = fs;          // 128
    float* lrun = fs + 128;    // 128
    float* pmax = fs + 256;    // 4*128
    float* psum = fs + 768;    // 4*128

    const int tid = threadIdx.x, w = tid >> 5, lane = tid & 31;
    const int g = lane >> 2, t2 = (lane & 3) * 2;
    const int h = blockIdx.x, qt = blockIdx.y, b = blockIdx.z;
    const int q0 = qt * 128;
    const size_t hb = (size_t)(b * NH + h) * NS;
    const u16* qhi = g_qhi + (hb + q0) * DP;
    const u16* qlo = g_qlo + (hb + q0) * DP;
    const u16* khi = g_khi + hb * DP;
    const u16* klo = g_klo + hb * DP;
    const u16* vhi = g_vhi + hb * DP;
    const u16* vlo = g_vlo + hb * DP;
    float* wrow = wbuf + (hb + q0) * NS;

    #pragma unroll
    for (int it = 0; it < 4; ++it) {
        int e = it * 256 + tid, r = e >> 3, c8 = (e & 7) * 8;
        *(uint4*)(QH + r * PIT + c8) = *(const uint4*)(qhi + (size_t)r * DP + c8);
        *(uint4*)(QL + r * PIT + c8) = *(const uint4*)(qlo + (size_t)r * DP + c8);
    }
    if (tid < 128) { mrun[tid] = -1e30f; lrun[tid] = 0.f; }

    const int wm = w >> 2, wn = w & 3;

    // ---------------- phase 1 ----------------
    for (int kt = 0; kt < 16; ++kt) {
        const int k0g = kt * 128;
        __syncthreads();
        #pragma unroll
        for (int it = 0; it < 4; ++it) {
            int e = it * 256 + tid, r = e >> 3, c8 = (e & 7) * 8;
            *(uint4*)(KH + r * PIT + c8) = *(const uint4*)(khi + (size_t)(k0g + r) * DP + c8);
            *(uint4*)(KL + r * PIT + c8) = *(const uint4*)(klo + (size_t)(k0g + r) * DP + c8);
        }
        __syncthreads();

        float dd[4][4][4];
        #pragma unroll
        for (int i = 0; i < 4; ++i)
            #pragma unroll
            for (int j = 0; j < 4; ++j)
                #pragma unroll
                for (int c = 0; c < 4; ++c) dd[i][j][c] = 0.f;

        #pragma unroll
        for (int ks = 0; ks < 4; ++ks) {
            const int kk = ks * 16;
            u32 ah[4][4], al[4][4], bh[4][2], bl[4][2];
            #pragma unroll
            for (int mt = 0; mt < 4; ++mt) {
                lda(ah[mt], QH, wm*64 + mt*16, kk, g, t2);
                lda(al[mt], QL, wm*64 + mt*16, kk, g, t2);
            }
            #pragma unroll
            for (int nt = 0; nt < 4; ++nt) {
                ldb(bh[nt], KH, wn*32 + nt*8, kk, g, t2);
                ldb(bl[nt], KL, wn*32 + nt*8, kk, g, t2);
            }
            #pragma unroll
            for (int mt = 0; mt < 4; ++mt)
                #pragma unroll
                for (int nt = 0; nt < 4; ++nt) {
                    mma_bf16(dd[mt][nt], ah[mt], bh[nt]);
                    mma_bf16(dd[mt][nt], ah[mt], bl[nt]);
                    mma_bf16(dd[mt][nt], al[mt], bh[nt]);
                }
        }
        #pragma unroll
        for (int i = 0; i < 4; ++i)
            #pragma unroll
            for (int j = 0; j < 4; ++j)
                #pragma unroll
                for (int c = 0; c < 4; ++c) dd[i][j][c] *= 0.125f;

        // tile row-max partials
        #pragma unroll
        for (int mt = 0; mt < 4; ++mt)
            #pragma unroll
            for (int hf = 0; hf < 2; ++hf) {
                int row = wm*64 + mt*16 + g + hf*8;
                float vm = -1e30f;
                #pragma unroll
                for (int nt = 0; nt < 4; ++nt)
                    vm = fmaxf(vm, fmaxf(dd[mt][nt][hf*2], dd[mt][nt][hf*2+1]));
                vm = fmaxf(vm, __shfl_xor_sync(0xffffffffu, vm, 1));
                vm = fmaxf(vm, __shfl_xor_sync(0xffffffffu, vm, 2));
                if ((lane & 3) == 0) pmax[wn*128 + row] = vm;
            }
        __syncthreads();
        // exp-sum partials + raw store
        #pragma unroll
        for (int mt = 0; mt < 4; ++mt)
            #pragma unroll
            for (int hf = 0; hf < 2; ++hf) {
                int row = wm*64 + mt*16 + g + hf*8;
                float tm = fmaxf(fmaxf(pmax[row], pmax[128+row]),
                                 fmaxf(pmax[256+row], pmax[384+row]));
                float mnew = fmaxf(mrun[row], tm);
                float ps = 0.f;
                #pragma unroll
                for (int nt = 0; nt < 4; ++nt) {
                    float a0 = dd[mt][nt][hf*2], a1 = dd[mt][nt][hf*2+1];
                    ps += __expf(a0 - mnew) + __expf(a1 - mnew);
                    *(float2*)(wrow + (size_t)row * NS + k0g + wn*32 + nt*8 + t2)
                        = make_float2(a0, a1);
                }
                ps += __shfl_xor_sync(0xffffffffu, ps, 1);
                ps += __shfl_xor_sync(0xffffffffu, ps, 2);
                if ((lane & 3) == 0) psum[wn*128 + row] = ps;
            }
        __syncthreads();
        if (tid < 128) {
            int row = tid;
            float tm = fmaxf(fmaxf(pmax[row], pmax[128+row]),
                             fmaxf(pmax[256+row], pmax[384+row]));
            float mnew = fmaxf(mrun[row], tm);
            lrun[row] = lrun[row] * __expf(mrun[row] - mnew)
                      + psum[row] + psum[128+row] + psum[256+row] + psum[384+row];
            mrun[row] = mnew;
        }
    }
    __syncthreads();
    if (tid < 128) lrun[tid] = 1.0f / lrun[tid];

    // ---------------- phase 2 ----------------
    const int wm2 = w >> 1, wn2 = w & 1;
    float da[2][4][4];
    #pragma unroll
    for (int i = 0; i < 2; ++i)
        #pragma unroll
        for (int j = 0; j < 4; ++j)
            #pragma unroll
            for (int c = 0; c < 4; ++c) da[i][j][c] = 0.f;

    for (int ch = 0; ch < 32; ++ch) {
        const int k0g = ch * 64;
        __syncthreads();
        // V chunk transposed into [d][key]
        #pragma unroll
        for (int it = 0; it < 4; ++it) {
            int e = it * 256 + tid, key = e >> 4, d4 = (e & 15) * 4;
            uint2 hv = *(const uint2*)(vhi + (size_t)(k0g + key) * DP + d4);
            uint2 lv = *(const uint2*)(vlo + (size_t)(k0g + key) * DP + d4);
            const u16* hp = (const u16*)&hv;
            const u16* lp = (const u16*)&lv;
            #pragma unroll
            for (int j = 0; j < 4; ++j) {
                VH[(d4 + j) * PIT + key] = hp[j];
                VL[(d4 + j) * PIT + key] = lp[j];
            }
        }
        // normalize (weights output) + split into W staging
        #pragma unroll
        for (int it = 0; it < 8; ++it) {
            int e = it * 256 + tid, r = e >> 4, c4 = (e & 15) * 4;
            float4 v = *(float4*)(wrow + (size_t)r * NS + k0g + c4);
            float mm = mrun[r], li = lrun[r];
            float4 wv;
            wv.x = __expf(v.x - mm) * li; wv.y = __expf(v.y - mm) * li;
            wv.z = __expf(v.z - mm) * li; wv.w = __expf(v.w - mm) * li;
            *(float4*)(wrow + (size_t)r * NS + k0g + c4) = wv;
            split_st(KH, KL, r * PIT + c4, wv);
        }
        __syncthreads();
        #pragma unroll
        for (int ks = 0; ks < 4; ++ks) {
            const int kk = ks * 16;
            u32 ah[2][4], al[2][4], bh[4][2], bl[4][2];
            #pragma unroll
            for (int mt = 0; mt < 2; ++mt) {
                lda(ah[mt], KH, wm2*32 + mt*16, kk, g, t2);
                lda(al[mt], KL, wm2*32 + mt*16, kk, g, t2);
            }
            #pragma unroll
            for (int nt = 0; nt < 4; ++nt) {
                ldb(bh[nt], VH, wn2*32 + nt*8, kk, g, t2);
                ldb(bl[nt], VL, wn2*32 + nt*8, kk, g, t2);
            }
            #pragma unroll
            for (int mt = 0; mt < 2; ++mt)
                #pragma unroll
                for (int nt = 0; nt < 4; ++nt) {
                    mma_bf16(da[mt][nt], ah[mt], bh[nt]);
                    mma_bf16(da[mt][nt], ah[mt], bl[nt]);
                    mma_bf16(da[mt][nt], al[mt], bh[nt]);
                }
        }
    }

    #pragma unroll
    for (int mt = 0; mt < 2; ++mt) {
        int r1 = wm2*32 + mt*16 + g, r2 = r1 + 8;
        #pragma unroll
        for (int nt = 0; nt < 4; ++nt) {
            int c = wn2*32 + nt*8 + t2;
            *(float2*)(g_attn + (size_t)(b*NS + q0 + r1) * ND + h*DP + c)
                = make_float2(da[mt][nt][0], da[mt][nt][1]);
            *(float2*)(g_attn + (size_t)(b*NS + q0 + r2) * ND + h*DP + c)
                = make_float2(da[mt][nt][2], da[mt][nt][3]);
        }
    }
}

// =============================================================================
extern "C" void kernel_launch(void* const* d_in, const int* in_sizes, int n_in,
                              void* d_out, int out_size)
{
    const float* q  = (const float*)d_in[0];
    const float* k  = (const float*)d_in[1];
    const float* v  = (const float*)d_in[2];
    const float* Wq = (const float*)d_in[4];
    const float* bq = (const float*)d_in[5];
    const float* Wk = (const float*)d_in[6];
    const float* bk = (const float*)d_in[7];
    const float* Wv = (const float*)d_in[8];
    const float* bv = (const float*)d_in[9];
    const float* Wo = (const float*)d_in[10];
    const float* bo = (const float*)d_in[11];

    float* out     = (float*)d_out;
    float* weights = out + (size_t)MROWS * ND;

    cudaFuncSetAttribute(proj_mma, cudaFuncAttributeMaxDynamicSharedMemorySize, PSM);
    cudaFuncSetAttribute(attn_mma, cudaFuncAttributeMaxDynamicSharedMemorySize, ASMB);

    dim3 gp(ND / 128, MROWS / 128);
    proj_mma<<<gp, 256, PSM>>>(q, Wq, bq, nullptr, 0);
    proj_mma<<<gp, 256, PSM>>>(k, Wk, bk, nullptr, 1);
    proj_mma<<<gp, 256, PSM>>>(v, Wv, bv, nullptr, 2);

    dim3 ga(NH, NS / 128, NB);
    attn_mma<<<ga, 256, ASMB>>>(weights);

    proj_mma<<<gp, 256, PSM>>>(nullptr, Wo, bo, out, 3);
}

// round 10
// speedup vs baseline: 2.5908x; 1.1239x over previous
#include <cuda_runtime.h>
#include <cuda_bf16.h>

#define NB 2
#define NS 2048
#define ND 1024
#define NH 16
#define DP 64
#define MROWS (NB*NS)
#define PIT 72

typedef unsigned int   u32;
typedef unsigned short u16;

__device__ __align__(16) u16   g_qhi[NB*NH*NS*DP];
__device__ __align__(16) u16   g_qlo[NB*NH*NS*DP];
__device__ __align__(16) u16   g_khi[NB*NH*NS*DP];
__device__ __align__(16) u16   g_klo[NB*NH*NS*DP];
__device__ __align__(16) u16   g_vthi[NB*NH*DP*NS];   // V transposed [B,H,d,S]
__device__ __align__(16) u16   g_vtlo[NB*NH*DP*NS];
__device__ __align__(16) float g_attn[MROWS*ND];

__device__ __forceinline__ void split1(float x, u16 &h, u16 &l) {
    __nv_bfloat16 hb = __float2bfloat16(x);
    h = __bfloat16_as_ushort(hb);
    l = __bfloat16_as_ushort(__float2bfloat16(x - __bfloat162float(hb)));
}
__device__ __forceinline__ u32 pck(u16 a, u16 b) { return (u32)a | ((u32)b << 16); }

__device__ __forceinline__ void mma_bf16(float* d, const u32* a, const u32* b) {
    asm volatile("mma.sync.aligned.m16n8k16.row.col.f32.bf16.bf16.f32 "
        "{%0,%1,%2,%3}, {%4,%5,%6,%7}, {%8,%9}, {%0,%1,%2,%3};"
        : "+f"(d[0]), "+f"(d[1]), "+f"(d[2]), "+f"(d[3])
        : "r"(a[0]), "r"(a[1]), "r"(a[2]), "r"(a[3]), "r"(b[0]), "r"(b[1]));
}
__device__ __forceinline__ void lda(u32* a, const u16* S, int row, int k, int g, int t2) {
    const u16* p = S + (row + g) * PIT + k + t2;
    a[0] = *(const u32*)p;
    a[1] = *(const u32*)(p + 8 * PIT);
    a[2] = *(const u32*)(p + 8);
    a[3] = *(const u32*)(p + 8 * PIT + 8);
}
__device__ __forceinline__ void ldb(u32* bf, const u16* S, int n, int k, int g, int t2) {
    const u16* p = S + (n + g) * PIT + k + t2;
    bf[0] = *(const u32*)p;
    bf[1] = *(const u32*)(p + 8);
}
__device__ __forceinline__ void split_st(u16* H, u16* L, int idx, float4 v) {
    u16 h0,l0,h1,l1,h2,l2,h3,l3;
    split1(v.x,h0,l0); split1(v.y,h1,l1); split1(v.z,h2,l2); split1(v.w,h3,l3);
    *(uint2*)(H + idx) = make_uint2(pck(h0,h1), pck(h2,h3));
    *(uint2*)(L + idx) = make_uint2(pck(l0,l1), pck(l2,l3));
}

#define CP16(dst, src) \
    asm volatile("cp.async.ca.shared.global [%0], [%1], 16;" :: "r"(dst), "l"(src))
#define CP_COMMIT() asm volatile("cp.async.commit_group;" ::: "memory")
#define CP_WAIT0()  asm volatile("cp.async.wait_group 0;" ::: "memory")

__device__ __forceinline__ u32 smem_u32(const void* p) {
    u32 a;
    asm("{ .reg .u64 t; cvta.to.shared.u64 t, %1; cvt.u32.u64 %0, t; }"
        : "=r"(a) : "l"(p));
    return a;
}

// =============================================================================
// Projection GEMM: Y[m,n] = sum_k X[m,k]*W[n,k] + b[n].
// 128x128 tile, 256 thr. modes 0/1 -> split bf16 Q/K [B,H,S,d];
// mode 2 -> split bf16 V transposed [B,H,d,S]; mode 3 -> f32 OutP.
// =============================================================================
#define PSM 73728
__global__ void __launch_bounds__(256)
proj_mma(const float* __restrict__ Xp, const float* __restrict__ W,
         const float* __restrict__ bias, float* __restrict__ OutP, int mode)
{
    extern __shared__ u16 sp[];
    u16 *AH = sp, *AL = sp + 9216, *BH = sp + 18432, *BL = sp + 27648;
    const float* X = (mode == 3) ? g_attn : Xp;
    const int tid = threadIdx.x, w = tid >> 5, lane = tid & 31;
    const int g = lane >> 2, t2 = (lane & 3) * 2;
    const int wm = w >> 2, wn = w & 3;
    const int n0 = blockIdx.x * 128, m0 = blockIdx.y * 128;

    float dd[4][4][4];
    #pragma unroll
    for (int i = 0; i < 4; ++i)
        #pragma unroll
        for (int j = 0; j < 4; ++j)
            #pragma unroll
            for (int c = 0; c < 4; ++c) dd[i][j][c] = 0.f;

    for (int kt = 0; kt < 16; ++kt) {
        const int k0 = kt * 64;
        __syncthreads();
        #pragma unroll
        for (int it = 0; it < 8; ++it) {
            int e = it * 256 + tid, r = e >> 4, c4 = (e & 15) * 4;
            float4 xv = *(const float4*)(X + (size_t)(m0 + r) * ND + k0 + c4);
            split_st(AH, AL, r * PIT + c4, xv);
            float4 wv = *(const float4*)(W + (size_t)(n0 + r) * ND + k0 + c4);
            split_st(BH, BL, r * PIT + c4, wv);
        }
        __syncthreads();
        #pragma unroll
        for (int ks = 0; ks < 4; ++ks) {
            const int kk = ks * 16;
            u32 ah[4][4], al[4][4], bh[4][2], bl[4][2];
            #pragma unroll
            for (int mt = 0; mt < 4; ++mt) {
                lda(ah[mt], AH, wm*64 + mt*16, kk, g, t2);
                lda(al[mt], AL, wm*64 + mt*16, kk, g, t2);
            }
            #pragma unroll
            for (int nt = 0; nt < 4; ++nt) {
                ldb(bh[nt], BH, wn*32 + nt*8, kk, g, t2);
                ldb(bl[nt], BL, wn*32 + nt*8, kk, g, t2);
            }
            #pragma unroll
            for (int mt = 0; mt < 4; ++mt)
                #pragma unroll
                for (int nt = 0; nt < 4; ++nt) {
                    mma_bf16(dd[mt][nt], ah[mt], bh[nt]);
                    mma_bf16(dd[mt][nt], ah[mt], bl[nt]);
                    mma_bf16(dd[mt][nt], al[mt], bh[nt]);
                }
        }
    }

    #pragma unroll
    for (int mt = 0; mt < 4; ++mt) {
        int r1 = m0 + wm*64 + mt*16 + g, r2 = r1 + 8;
        #pragma unroll
        for (int nt = 0; nt < 4; ++nt) {
            int c = n0 + wn*32 + nt*8 + t2;
            float2 bv = *(const float2*)(bias + c);
            float x0 = dd[mt][nt][0] + bv.x, x1 = dd[mt][nt][1] + bv.y;
            float x2 = dd[mt][nt][2] + bv.x, x3 = dd[mt][nt][3] + bv.y;
            if (mode == 0 || mode == 1) {
                u16* dh = (mode == 0) ? g_qhi : g_khi;
                u16* dl = (mode == 0) ? g_qlo : g_klo;
                int hh = c >> 6, cd = c & 63;
                size_t i1 = ((size_t)((r1 >> 11) * NH + hh) * NS + (r1 & 2047)) * DP + cd;
                size_t i2 = ((size_t)((r2 >> 11) * NH + hh) * NS + (r2 & 2047)) * DP + cd;
                u16 h0,l0,h1,l1;
                split1(x0,h0,l0); split1(x1,h1,l1);
                *(u32*)(dh + i1) = pck(h0,h1); *(u32*)(dl + i1) = pck(l0,l1);
                split1(x2,h0,l0); split1(x3,h1,l1);
                *(u32*)(dh + i2) = pck(h0,h1); *(u32*)(dl + i2) = pck(l0,l1);
            } else if (mode == 2) {
                // V transposed: [B,H,d,S]
                int hh = c >> 6, cd = c & 63;
                int tok1 = r1 & 2047, tok2 = r2 & 2047;
                size_t b1 = ((size_t)((r1 >> 11) * NH + hh) * DP + cd) * NS + tok1;
                size_t b2 = ((size_t)((r2 >> 11) * NH + hh) * DP + cd) * NS + tok2;
                u16 h0,l0,h1,l1;
                split1(x0,h0,l0); split1(x1,h1,l1);
                g_vthi[b1] = h0; g_vtlo[b1] = l0;
                g_vthi[b1 + NS] = h1; g_vtlo[b1 + NS] = l1;
                split1(x2,h0,l0); split1(x3,h1,l1);
                g_vthi[b2] = h0; g_vtlo[b2] = l0;
                g_vthi[b2 + NS] = h1; g_vtlo[b2 + NS] = l1;
            } else {
                *(float2*)(OutP + (size_t)r1 * ND + c) = make_float2(x0, x1);
                *(float2*)(OutP + (size_t)r2 * ND + c) = make_float2(x2, x3);
            }
        }
    }
}

// =============================================================================
// Fused attention per (b,h,128 q), 64-key chunks, cp.async double-buffered.
// smem (bytes): QH 0 /18432, QL 18432 (phase2: WH/WL)
//               Kbuf0H 36864, Kbuf0L 46080, Kbuf1H 55296, Kbuf1L 64512
//               (phase2: Vbuf0/Vbuf1 in same space)
//               fs 73728 (768 floats)  -> total 76800
// =============================================================================
#define ASMB 76800
__global__ void __launch_bounds__(256, 2)
attn_mma(float* __restrict__ wbuf)
{
    extern __shared__ u16 sp[];
    u16* QH = sp;             // also WH in phase 2
    u16* QL = sp + 9216;      // also WL
    float* fs   = (float*)(sp + 36864);
    float* mrow = fs;         // 128
    float* lrow = fs + 128;   // 128
    float* pm   = fs + 256;   // 2*128
    float* pl   = fs + 512;   // 2*128

    const u32 sb = smem_u32(sp);
    const int tid = threadIdx.x, w = tid >> 5, lane = tid & 31;
    const int g = lane >> 2, t2 = (lane & 3) * 2;
    const int h = blockIdx.x, qt = blockIdx.y, b = blockIdx.z;
    const int q0 = qt * 128;
    const size_t hb = (size_t)(b * NH + h) * NS;
    const u16* qhi = g_qhi + (hb + q0) * DP;
    const u16* qlo = g_qlo + (hb + q0) * DP;
    const u16* khi = g_khi + hb * DP;
    const u16* klo = g_klo + hb * DP;
    const u16* vthi = g_vthi + (size_t)(b * NH + h) * DP * NS;
    const u16* vtlo = g_vtlo + (size_t)(b * NH + h) * DP * NS;
    float* wrow = wbuf + (hb + q0) * NS;

    // load Q tile once
    #pragma unroll
    for (int it = 0; it < 4; ++it) {
        int e = it * 256 + tid, r = e >> 3, c8 = (e & 7) * 8;
        *(uint4*)(QH + r * PIT + c8) = *(const uint4*)(qhi + (size_t)r * DP + c8);
        *(uint4*)(QL + r * PIT + c8) = *(const uint4*)(qlo + (size_t)r * DP + c8);
    }

    const int wm = w >> 1, wn = w & 1;   // 4 row-groups x 2 col-groups

    // -------- issue first K copy --------
    {
        const u32 hbA = sb + 36864, lbA = hbA + 9216;
        #pragma unroll
        for (int it = 0; it < 2; ++it) {
            int e = it * 256 + tid, r = e >> 3, c8 = (e & 7) * 8;
            u32 off = (u32)(r * PIT + c8) * 2;
            CP16(hbA + off, khi + (size_t)r * DP + c8);
            CP16(lbA + off, klo + (size_t)r * DP + c8);
        }
        CP_COMMIT();
    }

    float mr[2][2], lr[2][2];
    #pragma unroll
    for (int i = 0; i < 2; ++i)
        #pragma unroll
        for (int j = 0; j < 2; ++j) { mr[i][j] = -1e30f; lr[i][j] = 0.f; }

    // ---------------- phase 1: 32 chunks of 64 keys ----------------
    for (int kt = 0; kt < 32; ++kt) {
        CP_WAIT0();
        __syncthreads();
        if (kt < 31) {
            const int nb = (kt + 1) & 1;
            const u32 hbA = sb + 36864 + nb * 18432, lbA = hbA + 9216;
            const int k0n = (kt + 1) * 64;
            #pragma unroll
            for (int it = 0; it < 2; ++it) {
                int e = it * 256 + tid, r = e >> 3, c8 = (e & 7) * 8;
                u32 off = (u32)(r * PIT + c8) * 2;
                CP16(hbA + off, khi + (size_t)(k0n + r) * DP + c8);
                CP16(lbA + off, klo + (size_t)(k0n + r) * DP + c8);
            }
            CP_COMMIT();
        }
        const u16* KH = sp + 18432 + (kt & 1) * 9216;
        const u16* KL = KH + 4608;
        const int k0 = kt * 64;

        float dd[2][4][4];
        #pragma unroll
        for (int i = 0; i < 2; ++i)
            #pragma unroll
            for (int j = 0; j < 4; ++j)
                #pragma unroll
                for (int c = 0; c < 4; ++c) dd[i][j][c] = 0.f;

        #pragma unroll
        for (int ks = 0; ks < 4; ++ks) {
            const int kk = ks * 16;
            u32 ah[2][4], al[2][4], bh[4][2], bl[4][2];
            #pragma unroll
            for (int mt = 0; mt < 2; ++mt) {
                lda(ah[mt], QH, wm*32 + mt*16, kk, g, t2);
                lda(al[mt], QL, wm*32 + mt*16, kk, g, t2);
            }
            #pragma unroll
            for (int nt = 0; nt < 4; ++nt) {
                ldb(bh[nt], KH, wn*32 + nt*8, kk, g, t2);
                ldb(bl[nt], KL, wn*32 + nt*8, kk, g, t2);
            }
            #pragma unroll
            for (int mt = 0; mt < 2; ++mt)
                #pragma unroll
                for (int nt = 0; nt < 4; ++nt) {
                    mma_bf16(dd[mt][nt], ah[mt], bh[nt]);
                    mma_bf16(dd[mt][nt], ah[mt], bl[nt]);
                    mma_bf16(dd[mt][nt], al[mt], bh[nt]);
                }
        }

        // scale + per-warp online stats (register-resident) + raw store
        #pragma unroll
        for (int mt = 0; mt < 2; ++mt)
            #pragma unroll
            for (int hf = 0; hf < 2; ++hf) {
                const int row = wm*32 + mt*16 + g + hf*8;
                float v[8];
                #pragma unroll
                for (int nt = 0; nt < 4; ++nt) {
                    v[nt*2]   = dd[mt][nt][hf*2]   * 0.125f;
                    v[nt*2+1] = dd[mt][nt][hf*2+1] * 0.125f;
                }
                float vm = v[0];
                #pragma unroll
                for (int i = 1; i < 8; ++i) vm = fmaxf(vm, v[i]);
                vm = fmaxf(vm, __shfl_xor_sync(0xffffffffu, vm, 1));
                vm = fmaxf(vm, __shfl_xor_sync(0xffffffffu, vm, 2));
                float mnew = fmaxf(mr[mt][hf], vm);
                float ps = 0.f;
                #pragma unroll
                for (int i = 0; i < 8; ++i) ps += __expf(v[i] - mnew);
                ps += __shfl_xor_sync(0xffffffffu, ps, 1);
                ps += __shfl_xor_sync(0xffffffffu, ps, 2);
                lr[mt][hf] = lr[mt][hf] * __expf(mr[mt][hf] - mnew) + ps;
                mr[mt][hf] = mnew;
                #pragma unroll
                for (int nt = 0; nt < 4; ++nt)
                    *(float2*)(wrow + (size_t)row * NS + k0 + wn*32 + nt*8 + t2)
                        = make_float2(v[nt*2], v[nt*2+1]);
            }
    }

    // merge the 2 column-group partials per row
    if ((lane & 3) == 0) {
        #pragma unroll
        for (int mt = 0; mt < 2; ++mt)
            #pragma unroll
            for (int hf = 0; hf < 2; ++hf) {
                const int row = wm*32 + mt*16 + g + hf*8;
                pm[wn*128 + row] = mr[mt][hf];
                pl[wn*128 + row] = lr[mt][hf];
            }
    }
    __syncthreads();
    if (tid < 128) {
        float m0 = pm[tid], m1 = pm[128 + tid];
        float mf = fmaxf(m0, m1);
        float l = pl[tid] * __expf(m0 - mf) + pl[128 + tid] * __expf(m1 - mf);
        mrow[tid] = mf;
        lrow[tid] = 1.0f / l;
    }
    __syncthreads();

    // -------- issue first V copy (reuses K buffer space) --------
    {
        const u32 hbA = sb + 36864, lbA = hbA + 9216;
        #pragma unroll
        for (int it = 0; it < 2; ++it) {
            int e = it * 256 + tid, r = e >> 3, c8 = (e & 7) * 8;
            u32 off = (u32)(r * PIT + c8) * 2;
            CP16(hbA + off, vthi + (size_t)r * NS + c8);
            CP16(lbA + off, vtlo + (size_t)r * NS + c8);
        }
        CP_COMMIT();
    }

    const int wm2 = w >> 1, wn2 = w & 1;
    float da[2][4][4];
    #pragma unroll
    for (int i = 0; i < 2; ++i)
        #pragma unroll
        for (int j = 0; j < 4; ++j)
            #pragma unroll
            for (int c = 0; c < 4; ++c) da[i][j][c] = 0.f;

    // ---------------- phase 2: 32 chunks of 64 keys ----------------
    for (int ch = 0; ch < 32; ++ch) {
        CP_WAIT0();
        __syncthreads();
        if (ch < 31) {
            const int nb = (ch + 1) & 1;
            const u32 hbA = sb + 36864 + nb * 18432, lbA = hbA + 9216;
            const int k0n = (ch + 1) * 64;
            #pragma unroll
            for (int it = 0; it < 2; ++it) {
                int e = it * 256 + tid, r = e >> 3, c8 = (e & 7) * 8;
                u32 off = (u32)(r * PIT + c8) * 2;
                CP16(hbA + off, vthi + (size_t)r * NS + k0n + c8);
                CP16(lbA + off, vtlo + (size_t)r * NS + k0n + c8);
            }
            CP_COMMIT();
        }
        const int k0 = ch * 64;
        // normalize this 128x64 chunk (weights output) + split into WH/WL
        #pragma unroll
        for (int it = 0; it < 8; ++it) {
            int e = it * 256 + tid, r = e >> 4, c4 = (e & 15) * 4;
            float4 vv = *(float4*)(wrow + (size_t)r * NS + k0 + c4);
            float mm = mrow[r], li = lrow[r];
            float4 ww;
            ww.x = __expf(vv.x - mm) * li; ww.y = __expf(vv.y - mm) * li;
            ww.z = __expf(vv.z - mm) * li; ww.w = __expf(vv.w - mm) * li;
            *(float4*)(wrow + (size_t)r * NS + k0 + c4) = ww;
            split_st(QH, QL, r * PIT + c4, ww);
        }
        __syncthreads();

        const u16* VH = sp + 18432 + (ch & 1) * 9216;
        const u16* VL = VH + 4608;
        #pragma unroll
        for (int ks = 0; ks < 4; ++ks) {
            const int kk = ks * 16;
            u32 ah[2][4], al[2][4], bh[4][2], bl[4][2];
            #pragma unroll
            for (int mt = 0; mt < 2; ++mt) {
                lda(ah[mt], QH, wm2*32 + mt*16, kk, g, t2);
                lda(al[mt], QL, wm2*32 + mt*16, kk, g, t2);
            }
            #pragma unroll
            for (int nt = 0; nt < 4; ++nt) {
                ldb(bh[nt], VH, wn2*32 + nt*8, kk, g, t2);
                ldb(bl[nt], VL, wn2*32 + nt*8, kk, g, t2);
            }
            #pragma unroll
            for (int mt = 0; mt < 2; ++mt)
                #pragma unroll
                for (int nt = 0; nt < 4; ++nt) {
                    mma_bf16(da[mt][nt], ah[mt], bh[nt]);
                    mma_bf16(da[mt][nt], ah[mt], bl[nt]);
                    mma_bf16(da[mt][nt], al[mt], bh[nt]);
                }
        }
    }

    #pragma unroll
    for (int mt = 0; mt < 2; ++mt) {
        int r1 = wm2*32 + mt*16 + g, r2 = r1 + 8;
        #pragma unroll
        for (int nt = 0; nt < 4; ++nt) {
            int c = wn2*32 + nt*8 + t2;
            *(float2*)(g_attn + (size_t)(b*NS + q0 + r1) * ND + h*DP + c)
                = make_float2(da[mt][nt][0], da[mt][nt][1]);
            *(float2*)(g_attn + (size_t)(b*NS + q0 + r2) * ND + h*DP + c)
                = make_float2(da[mt][nt][2], da[mt][nt][3]);
        }
    }
}

// =============================================================================
extern "C" void kernel_launch(void* const* d_in, const int* in_sizes, int n_in,
                              void* d_out, int out_size)
{
    const float* q  = (const float*)d_in[0];
    const float* k  = (const float*)d_in[1];
    const float* v  = (const float*)d_in[2];
    const float* Wq = (const float*)d_in[4];
    const float* bq = (const float*)d_in[5];
    const float* Wk = (const float*)d_in[6];
    const float* bk = (const float*)d_in[7];
    const float* Wv = (const float*)d_in[8];
    const float* bv = (const float*)d_in[9];
    const float* Wo = (const float*)d_in[10];
    const float* bo = (const float*)d_in[11];

    float* out     = (float*)d_out;
    float* weights = out + (size_t)MROWS * ND;

    cudaFuncSetAttribute(proj_mma, cudaFuncAttributeMaxDynamicSharedMemorySize, PSM);
    cudaFuncSetAttribute(attn_mma, cudaFuncAttributeMaxDynamicSharedMemorySize, ASMB);

    dim3 gp(ND / 128, MROWS / 128);
    proj_mma<<<gp, 256, PSM>>>(q, Wq, bq, nullptr, 0);
    proj_mma<<<gp, 256, PSM>>>(k, Wk, bk, nullptr, 1);
    proj_mma<<<gp, 256, PSM>>>(v, Wv, bv, nullptr, 2);

    dim3 ga(NH, NS / 128, NB);
    attn_mma<<<ga, 256, ASMB>>>(weights);

    proj_mma<<<gp, 256, PSM>>>(nullptr, Wo, bo, out, 3);
}

// round 11
// speedup vs baseline: 2.6495x; 1.0227x over previous
#include <cuda_runtime.h>
#include <cuda_bf16.h>

#define NB 2
#define NS 2048
#define ND 1024
#define NH 16
#define DP 64
#define MROWS (NB*NS)
#define PIT 72

typedef unsigned int   u32;
typedef unsigned short u16;

__device__ __align__(16) u16   g_qhi[NB*NH*NS*DP];
__device__ __align__(16) u16   g_qlo[NB*NH*NS*DP];
__device__ __align__(16) u16   g_khi[NB*NH*NS*DP];
__device__ __align__(16) u16   g_klo[NB*NH*NS*DP];
__device__ __align__(16) u16   g_vthi[NB*NH*DP*NS];   // V transposed [B,H,d,S]
__device__ __align__(16) u16   g_vtlo[NB*NH*DP*NS];
__device__ __align__(16) float g_attn[MROWS*ND];

__device__ __forceinline__ void split1(float x, u16 &h, u16 &l) {
    __nv_bfloat16 hb = __float2bfloat16(x);
    h = __bfloat16_as_ushort(hb);
    l = __bfloat16_as_ushort(__float2bfloat16(x - __bfloat162float(hb)));
}
__device__ __forceinline__ u32 pck(u16 a, u16 b) { return (u32)a | ((u32)b << 16); }

__device__ __forceinline__ void mma_bf16(float* d, const u32* a, const u32* b) {
    asm volatile("mma.sync.aligned.m16n8k16.row.col.f32.bf16.bf16.f32 "
        "{%0,%1,%2,%3}, {%4,%5,%6,%7}, {%8,%9}, {%0,%1,%2,%3};"
        : "+f"(d[0]), "+f"(d[1]), "+f"(d[2]), "+f"(d[3])
        : "r"(a[0]), "r"(a[1]), "r"(a[2]), "r"(a[3]), "r"(b[0]), "r"(b[1]));
}
__device__ __forceinline__ void lda_p(u32* a, const u16* S, int row, int k,
                                      int g, int t2, int p) {
    const u16* q = S + (row + g) * p + k + t2;
    a[0] = *(const u32*)q;
    a[1] = *(const u32*)(q + 8 * p);
    a[2] = *(const u32*)(q + 8);
    a[3] = *(const u32*)(q + 8 * p + 8);
}
__device__ __forceinline__ void ldb_p(u32* bf, const u16* S, int n, int k,
                                      int g, int t2, int p) {
    const u16* q = S + (n + g) * p + k + t2;
    bf[0] = *(const u32*)q;
    bf[1] = *(const u32*)(q + 8);
}
__device__ __forceinline__ void split_st(u16* H, u16* L, int idx, float4 v) {
    u16 h0,l0,h1,l1,h2,l2,h3,l3;
    split1(v.x,h0,l0); split1(v.y,h1,l1); split1(v.z,h2,l2); split1(v.w,h3,l3);
    *(uint2*)(H + idx) = make_uint2(pck(h0,h1), pck(h2,h3));
    *(uint2*)(L + idx) = make_uint2(pck(l0,l1), pck(l2,l3));
}

#define CP16(dst, src) \
    asm volatile("cp.async.ca.shared.global [%0], [%1], 16;" :: "r"(dst), "l"(src))
#define CP_COMMIT() asm volatile("cp.async.commit_group;" ::: "memory")
#define CP_WAIT0()  asm volatile("cp.async.wait_group 0;" ::: "memory")

__device__ __forceinline__ u32 smem_u32(const void* p) {
    u32 a;
    asm("{ .reg .u64 t; cvta.to.shared.u64 t, %1; cvt.u32.u64 %0, t; }"
        : "=r"(a) : "l"(p));
    return a;
}

// =============================================================================
// Projection GEMM (unchanged from R10).
// =============================================================================
#define PSM 73728
__global__ void __launch_bounds__(256)
proj_mma(const float* __restrict__ Xp, const float* __restrict__ W,
         const float* __restrict__ bias, float* __restrict__ OutP, int mode)
{
    extern __shared__ u16 sp[];
    u16 *AH = sp, *AL = sp + 9216, *BH = sp + 18432, *BL = sp + 27648;
    const float* X = (mode == 3) ? g_attn : Xp;
    const int tid = threadIdx.x, w = tid >> 5, lane = tid & 31;
    const int g = lane >> 2, t2 = (lane & 3) * 2;
    const int wm = w >> 2, wn = w & 3;
    const int n0 = blockIdx.x * 128, m0 = blockIdx.y * 128;

    float dd[4][4][4];
    #pragma unroll
    for (int i = 0; i < 4; ++i)
        #pragma unroll
        for (int j = 0; j < 4; ++j)
            #pragma unroll
            for (int c = 0; c < 4; ++c) dd[i][j][c] = 0.f;

    for (int kt = 0; kt < 16; ++kt) {
        const int k0 = kt * 64;
        __syncthreads();
        #pragma unroll
        for (int it = 0; it < 8; ++it) {
            int e = it * 256 + tid, r = e >> 4, c4 = (e & 15) * 4;
            float4 xv = *(const float4*)(X + (size_t)(m0 + r) * ND + k0 + c4);
            split_st(AH, AL, r * PIT + c4, xv);
            float4 wv = *(const float4*)(W + (size_t)(n0 + r) * ND + k0 + c4);
            split_st(BH, BL, r * PIT + c4, wv);
        }
        __syncthreads();
        #pragma unroll
        for (int ks = 0; ks < 4; ++ks) {
            const int kk = ks * 16;
            u32 ah[4][4], al[4][4], bh[4][2], bl[4][2];
            #pragma unroll
            for (int mt = 0; mt < 4; ++mt) {
                lda_p(ah[mt], AH, wm*64 + mt*16, kk, g, t2, PIT);
                lda_p(al[mt], AL, wm*64 + mt*16, kk, g, t2, PIT);
            }
            #pragma unroll
            for (int nt = 0; nt < 4; ++nt) {
                ldb_p(bh[nt], BH, wn*32 + nt*8, kk, g, t2, PIT);
                ldb_p(bl[nt], BL, wn*32 + nt*8, kk, g, t2, PIT);
            }
            #pragma unroll
            for (int mt = 0; mt < 4; ++mt)
                #pragma unroll
                for (int nt = 0; nt < 4; ++nt) {
                    mma_bf16(dd[mt][nt], ah[mt], bh[nt]);
                    mma_bf16(dd[mt][nt], ah[mt], bl[nt]);
                    mma_bf16(dd[mt][nt], al[mt], bh[nt]);
                }
        }
    }

    #pragma unroll
    for (int mt = 0; mt < 4; ++mt) {
        int r1 = m0 + wm*64 + mt*16 + g, r2 = r1 + 8;
        #pragma unroll
        for (int nt = 0; nt < 4; ++nt) {
            int c = n0 + wn*32 + nt*8 + t2;
            float2 bv = *(const float2*)(bias + c);
            float x0 = dd[mt][nt][0] + bv.x, x1 = dd[mt][nt][1] + bv.y;
            float x2 = dd[mt][nt][2] + bv.x, x3 = dd[mt][nt][3] + bv.y;
            if (mode == 0 || mode == 1) {
                u16* dh = (mode == 0) ? g_qhi : g_khi;
                u16* dl = (mode == 0) ? g_qlo : g_klo;
                int hh = c >> 6, cd = c & 63;
                size_t i1 = ((size_t)((r1 >> 11) * NH + hh) * NS + (r1 & 2047)) * DP + cd;
                size_t i2 = ((size_t)((r2 >> 11) * NH + hh) * NS + (r2 & 2047)) * DP + cd;
                u16 h0,l0,h1,l1;
                split1(x0,h0,l0); split1(x1,h1,l1);
                *(u32*)(dh + i1) = pck(h0,h1); *(u32*)(dl + i1) = pck(l0,l1);
                split1(x2,h0,l0); split1(x3,h1,l1);
                *(u32*)(dh + i2) = pck(h0,h1); *(u32*)(dl + i2) = pck(l0,l1);
            } else if (mode == 2) {
                int hh = c >> 6, cd = c & 63;
                int tok1 = r1 & 2047, tok2 = r2 & 2047;
                size_t b1 = ((size_t)((r1 >> 11) * NH + hh) * DP + cd) * NS + tok1;
                size_t b2 = ((size_t)((r2 >> 11) * NH + hh) * DP + cd) * NS + tok2;
                u16 h0,l0,h1,l1;
                split1(x0,h0,l0); split1(x1,h1,l1);
                g_vthi[b1] = h0; g_vtlo[b1] = l0;
                g_vthi[b1 + NS] = h1; g_vtlo[b1 + NS] = l1;
                split1(x2,h0,l0); split1(x3,h1,l1);
                g_vthi[b2] = h0; g_vtlo[b2] = l0;
                g_vthi[b2 + NS] = h1; g_vtlo[b2 + NS] = l1;
            } else {
                *(float2*)(OutP + (size_t)r1 * ND + c) = make_float2(x0, x1);
                *(float2*)(OutP + (size_t)r2 * ND + c) = make_float2(x2, x3);
            }
        }
    }
}

// =============================================================================
// Fused attention v3: recompute, no raw-logit round trip.
// 32-key chunks. 8 warps; warp w owns q rows w*16 + {g, g+8}.
// Phase 1: S stats only (register online max/sum). Phase 2: recompute S
// (bit-identical), w=exp(s-m)/l -> gmem (ONLY write) + bf16 hi/lo -> smem,
// A += W.V (3-term) with V^T hi/lo from cp.async.
//
// smem (u16 offsets): QH 0, QL 9216;
//   KB[i]=18432+i*4608 (KH | KL+2304); VB[i]=27648+i*5120 (VH | VL+2560);
//   WH 37888, WL 43008; fs(f32) @48128: mrow 128, lrow 128.  total 97280 B.
// =============================================================================
#define ASMB 97280
#define PITW 40
__global__ void __launch_bounds__(256, 2)
attn_mma(float* __restrict__ wbuf)
{
    extern __shared__ u16 sp[];
    u16* QH = sp;
    u16* QL = sp + 9216;
    u16* WH = sp + 37888;
    u16* WL = sp + 43008;
    float* mrow = (float*)(sp + 48128);
    float* lrow = mrow + 128;

    const u32 sb = smem_u32(sp);
    const int tid = threadIdx.x, w = tid >> 5, lane = tid & 31;
    const int g = lane >> 2, t2 = (lane & 3) * 2;
    const int h = blockIdx.x, qt = blockIdx.y, b = blockIdx.z;
    const int q0 = qt * 128;
    const size_t hb = (size_t)(b * NH + h) * NS;
    const u16* qhi = g_qhi + (hb + q0) * DP;
    const u16* qlo = g_qlo + (hb + q0) * DP;
    const u16* khi = g_khi + hb * DP;
    const u16* klo = g_klo + hb * DP;
    const u16* vthi = g_vthi + (size_t)(b * NH + h) * DP * NS;
    const u16* vtlo = g_vtlo + (size_t)(b * NH + h) * DP * NS;
    float* wrow = wbuf + (hb + q0) * NS;

    // Q tile resident (hi/lo)
    #pragma unroll
    for (int it = 0; it < 4; ++it) {
        int e = it * 256 + tid, r = e >> 3, c8 = (e & 7) * 8;
        *(uint4*)(QH + r * PIT + c8) = *(const uint4*)(qhi + (size_t)r * DP + c8);
        *(uint4*)(QL + r * PIT + c8) = *(const uint4*)(qlo + (size_t)r * DP + c8);
    }

    // K chunk copy helper indices (1 hi + 1 lo CP16 per thread)
    const int kr = tid >> 3, kc = (tid & 7) * 8;
    // V chunk copy (1 hi + 1 lo per thread)
    const int vd = tid >> 2, vc = (tid & 3) * 8;

    // ---- issue K chunk 0 ----
    {
        const u32 kh0 = sb + (18432u) * 2, kl0 = kh0 + 4608;
        CP16(kh0 + (u32)(kr * PIT + kc) * 2, khi + (size_t)kr * DP + kc);
        CP16(kl0 + (u32)(kr * PIT + kc) * 2, klo + (size_t)kr * DP + kc);
        CP_COMMIT();
    }

    float mr[2] = {-1e30f, -1e30f}, lr[2] = {0.f, 0.f};

    // ================= phase 1: stats only =================
    for (int kt = 0; kt < 64; ++kt) {
        CP_WAIT0();
        __syncthreads();
        if (kt < 63) {
            const u32 khb = sb + (18432u + ((kt + 1) & 1) * 4608) * 2;
            const int k0n = (kt + 1) * 32;
            CP16(khb + (u32)(kr * PIT + kc) * 2, khi + (size_t)(k0n + kr) * DP + kc);
            CP16(khb + 4608 + (u32)(kr * PIT + kc) * 2, klo + (size_t)(k0n + kr) * DP + kc);
            CP_COMMIT();
        }
        const u16* KH = sp + 18432 + (kt & 1) * 4608;
        const u16* KL = KH + 2304;

        float dd[4][4];
        #pragma unroll
        for (int j = 0; j < 4; ++j)
            #pragma unroll
            for (int c = 0; c < 4; ++c) dd[j][c] = 0.f;

        #pragma unroll
        for (int ks = 0; ks < 4; ++ks) {
            const int kk = ks * 16;
            u32 ah[4], al[4], bh[4][2], bl[4][2];
            lda_p(ah, QH, w*16, kk, g, t2, PIT);
            lda_p(al, QL, w*16, kk, g, t2, PIT);
            #pragma unroll
            for (int nt = 0; nt < 4; ++nt) {
                ldb_p(bh[nt], KH, nt*8, kk, g, t2, PIT);
                ldb_p(bl[nt], KL, nt*8, kk, g, t2, PIT);
            }
            #pragma unroll
            for (int nt = 0; nt < 4; ++nt) {
                mma_bf16(dd[nt], ah, bh[nt]);
                mma_bf16(dd[nt], ah, bl[nt]);
                mma_bf16(dd[nt], al, bh[nt]);
            }
        }
        #pragma unroll
        for (int j = 0; j < 4; ++j)
            #pragma unroll
            for (int c = 0; c < 4; ++c) dd[j][c] *= 0.125f;

        #pragma unroll
        for (int hf = 0; hf < 2; ++hf) {
            float vm = dd[0][hf*2];
            #pragma unroll
            for (int nt = 0; nt < 4; ++nt)
                vm = fmaxf(vm, fmaxf(dd[nt][hf*2], dd[nt][hf*2+1]));
            vm = fmaxf(vm, __shfl_xor_sync(0xffffffffu, vm, 1));
            vm = fmaxf(vm, __shfl_xor_sync(0xffffffffu, vm, 2));
            float mnew = fmaxf(mr[hf], vm);
            float ps = 0.f;
            #pragma unroll
            for (int nt = 0; nt < 4; ++nt)
                ps += __expf(dd[nt][hf*2] - mnew) + __expf(dd[nt][hf*2+1] - mnew);
            ps += __shfl_xor_sync(0xffffffffu, ps, 1);
            ps += __shfl_xor_sync(0xffffffffu, ps, 2);
            lr[hf] = lr[hf] * __expf(mr[hf] - mnew) + ps;
            mr[hf] = mnew;
        }
    }

    // publish per-row stats (each row owned by exactly one warp)
    if ((lane & 3) == 0) {
        #pragma unroll
        for (int hf = 0; hf < 2; ++hf) {
            int row = w*16 + g + hf*8;
            mrow[row] = mr[hf];
            lrow[row] = lr[hf];
        }
    }
    __syncthreads();
    if (tid < 128) lrow[tid] = 1.0f / lrow[tid];
    __syncthreads();

    // ---- issue K+V chunk 0 for phase 2 ----
    {
        const u32 kh0 = sb + (18432u) * 2;
        const u32 vh0 = sb + (27648u) * 2;
        CP16(kh0 + (u32)(kr * PIT + kc) * 2, khi + (size_t)kr * DP + kc);
        CP16(kh0 + 4608 + (u32)(kr * PIT + kc) * 2, klo + (size_t)kr * DP + kc);
        CP16(vh0 + (u32)(vd * PITW + vc) * 2, vthi + (size_t)vd * NS + vc);
        CP16(vh0 + 5120 + (u32)(vd * PITW + vc) * 2, vtlo + (size_t)vd * NS + vc);
        CP_COMMIT();
    }

    float da[8][4];
    #pragma unroll
    for (int j = 0; j < 8; ++j)
        #pragma unroll
        for (int c = 0; c < 4; ++c) da[j][c] = 0.f;

    // ================= phase 2: recompute + w store + A.V =================
    for (int ch = 0; ch < 64; ++ch) {
        CP_WAIT0();
        __syncthreads();
        if (ch < 63) {
            const int nb = (ch + 1) & 1;
            const u32 khb = sb + (18432u + nb * 4608) * 2;
            const u32 vhb = sb + (27648u + nb * 5120) * 2;
            const int k0n = (ch + 1) * 32;
            CP16(khb + (u32)(kr * PIT + kc) * 2, khi + (size_t)(k0n + kr) * DP + kc);
            CP16(khb + 4608 + (u32)(kr * PIT + kc) * 2, klo + (size_t)(k0n + kr) * DP + kc);
            CP16(vhb + (u32)(vd * PITW + vc) * 2, vthi + (size_t)vd * NS + k0n + vc);
            CP16(vhb + 5120 + (u32)(vd * PITW + vc) * 2, vtlo + (size_t)vd * NS + k0n + vc);
            CP_COMMIT();
        }
        const u16* KH = sp + 18432 + (ch & 1) * 4608;
        const u16* KL = KH + 2304;
        const u16* VH = sp + 27648 + (ch & 1) * 5120;
        const u16* VL = VH + 2560;
        const int k0 = ch * 32;

        // recompute S, bit-identical to phase 1
        float dd[4][4];
        #pragma unroll
        for (int j = 0; j < 4; ++j)
            #pragma unroll
            for (int c = 0; c < 4; ++c) dd[j][c] = 0.f;
        #pragma unroll
        for (int ks = 0; ks < 4; ++ks) {
            const int kk = ks * 16;
            u32 ah[4], al[4], bh[4][2], bl[4][2];
            lda_p(ah, QH, w*16, kk, g, t2, PIT);
            lda_p(al, QL, w*16, kk, g, t2, PIT);
            #pragma unroll
            for (int nt = 0; nt < 4; ++nt) {
                ldb_p(bh[nt], KH, nt*8, kk, g, t2, PIT);
                ldb_p(bl[nt], KL, nt*8, kk, g, t2, PIT);
            }
            #pragma unroll
            for (int nt = 0; nt < 4; ++nt) {
                mma_bf16(dd[nt], ah, bh[nt]);
                mma_bf16(dd[nt], ah, bl[nt]);
                mma_bf16(dd[nt], al, bh[nt]);
            }
        }
        #pragma unroll
        for (int j = 0; j < 4; ++j)
            #pragma unroll
            for (int c = 0; c < 4; ++c) dd[j][c] *= 0.125f;

        // normalize -> weights gmem (only write) + bf16 hi/lo staging in smem
        #pragma unroll
        for (int hf = 0; hf < 2; ++hf) {
            const int row = w*16 + g + hf*8;
            const float mm = mrow[row], li = lrow[row];
            #pragma unroll
            for (int nt = 0; nt < 4; ++nt) {
                float w0 = __expf(dd[nt][hf*2]   - mm) * li;
                float w1 = __expf(dd[nt][hf*2+1] - mm) * li;
                *(float2*)(wrow + (size_t)row * NS + k0 + nt*8 + t2)
                    = make_float2(w0, w1);
                u16 h0,l0,h1,l1;
                split1(w0,h0,l0); split1(w1,h1,l1);
                const int idx = row * PITW + nt*8 + t2;
                *(u32*)(WH + idx) = pck(h0,h1);
                *(u32*)(WL + idx) = pck(l0,l1);
            }
        }
        __syncthreads();

        // A += W . V   (3-term, V^T [d][key])
        #pragma unroll
        for (int ks = 0; ks < 2; ++ks) {
            const int kk = ks * 16;
            u32 awh[4], awl[4];
            lda_p(awh, WH, w*16, kk, g, t2, PITW);
            lda_p(awl, WL, w*16, kk, g, t2, PITW);
            #pragma unroll
            for (int nt2 = 0; nt2 < 8; ++nt2) {
                u32 bh2[2], bl2[2];
                ldb_p(bh2, VH, nt2*8, kk, g, t2, PITW);
                ldb_p(bl2, VL, nt2*8, kk, g, t2, PITW);
                mma_bf16(da[nt2], awh, bh2);
                mma_bf16(da[nt2], awh, bl2);
                mma_bf16(da[nt2], awl, bh2);
            }
        }
    }

    // epilogue: attn rows -> g_attn [B*S, H*d]
    #pragma unroll
    for (int hf = 0; hf < 2; ++hf) {
        const int row = w*16 + g + hf*8;
        float* dst = g_attn + (size_t)(b*NS + q0 + row) * ND + h * DP;
        #pragma unroll
        for (int nt2 = 0; nt2 < 8; ++nt2)
            *(float2*)(dst + nt2*8 + t2)
                = make_float2(da[nt2][hf*2], da[nt2][hf*2+1]);
    }
}

// =============================================================================
extern "C" void kernel_launch(void* const* d_in, const int* in_sizes, int n_in,
                              void* d_out, int out_size)
{
    const float* q  = (const float*)d_in[0];
    const float* k  = (const float*)d_in[1];
    const float* v  = (const float*)d_in[2];
    const float* Wq = (const float*)d_in[4];
    const float* bq = (const float*)d_in[5];
    const float* Wk = (const float*)d_in[6];
    const float* bk = (const float*)d_in[7];
    const float* Wv = (const float*)d_in[8];
    const float* bv = (const float*)d_in[9];
    const float* Wo = (const float*)d_in[10];
    const float* bo = (const float*)d_in[11];

    float* out     = (float*)d_out;
    float* weights = out + (size_t)MROWS * ND;

    cudaFuncSetAttribute(proj_mma, cudaFuncAttributeMaxDynamicSharedMemorySize, PSM);
    cudaFuncSetAttribute(attn_mma, cudaFuncAttributeMaxDynamicSharedMemorySize, ASMB);

    dim3 gp(ND / 128, MROWS / 128);
    proj_mma<<<gp, 256, PSM>>>(q, Wq, bq, nullptr, 0);
    proj_mma<<<gp, 256, PSM>>>(k, Wk, bk, nullptr, 1);
    proj_mma<<<gp, 256, PSM>>>(v, Wv, bv, nullptr, 2);

    dim3 ga(NH, NS / 128, NB);
    attn_mma<<<ga, 256, ASMB>>>(weights);

    proj_mma<<<gp, 256, PSM>>>(nullptr, Wo, bo, out, 3);
}